// round 4
// baseline (speedup 1.0000x reference)
#include <cuda_runtime.h>
#include <math.h>

#define BATCH 2
#define SEQ   1024
#define DM    1024
#define NH    16
#define DK    64
#define NG    4
#define HPG   4
#define DFF   4096
#define NE    8
#define NTOK  (BATCH*SEQ)      /* 2048 */
#define NASSIGN (NTOK*2)       /* 4096 */

/* ------------------------- scratch (device globals) ------------------------ */
__device__ float g_xr[NTOK*DM];          /* rmsnorm1 + rope output      8 MB */
__device__ float g_q [NTOK*DM];          /* Q projection                8 MB */
__device__ float g_k [NTOK*NG*DK];       /* K projection                2 MB */
__device__ float g_v [NTOK*NG*DK];       /* V projection                2 MB */
__device__ float g_attn[NTOK*DM];        /* attention output            8 MB */
__device__ float g_hn[NTOK*DM];          /* rmsnorm2 output             8 MB */
__device__ float g_h1[(size_t)NASSIGN*DFF]; /* expert h1 / fused h     64 MB */
__device__ float g_h2[(size_t)NASSIGN*DFF]; /* expert h2               64 MB */
__device__ float g_eo[NASSIGN*DM];       /* expert outputs             16 MB */
__device__ int   g_cnt[NE];
__device__ int   g_off[NE+1];
__device__ int   g_cur[NE];
__device__ int   g_tok[NASSIGN];         /* assignment row -> token */
__device__ int   g_tidx[NTOK*2];         /* token -> expert idx (top2) */
__device__ float g_twgt[NTOK*2];         /* token -> softmax weight (top2) */
__device__ int   g_trow[NTOK*2];         /* token -> assignment rows */

/* ------------------------------ small kernels ------------------------------ */

__global__ void k_zero() {
    if (threadIdx.x < NE) g_cnt[threadIdx.x] = 0;
}

/* rmsnorm(x, w) followed by RoPE over the full d_model vector (half = 512).
   out[k]      = xe[k]*cos - xo[k]*sin
   out[512+k]  = xe[k]*sin + xo[k]*cos,  xe=xn[2k], xo=xn[2k+1] */
__global__ void k_norm_rope(const float* __restrict__ x,
                            const float* __restrict__ w) {
    int row = blockIdx.x;            /* token index b*SEQ+s */
    int s   = row % SEQ;
    __shared__ float xs[DM];
    __shared__ float red[256];
    const float* xp = x + (size_t)row * DM;
    float ss = 0.f;
    for (int d = threadIdx.x; d < DM; d += 256) {
        float v = xp[d]; xs[d] = v; ss += v * v;
    }
    red[threadIdx.x] = ss; __syncthreads();
    for (int st = 128; st > 0; st >>= 1) {
        if (threadIdx.x < st) red[threadIdx.x] += red[threadIdx.x + st];
        __syncthreads();
    }
    float inv = rsqrtf(red[0] / (float)DM + 1e-6f);
    float* op = g_xr + (size_t)row * DM;
    for (int k = threadIdx.x; k < DM / 2; k += 256) {
        float theta = powf(10000.f, -(float)k / (float)(DM / 2));
        float ang = (float)s * theta;
        float sn, cs; sincosf(ang, &sn, &cs);
        float xe = xs[2 * k]     * inv * w[2 * k];
        float xo = xs[2 * k + 1] * inv * w[2 * k + 1];
        op[k]          = xe * cs - xo * sn;
        op[DM / 2 + k] = xe * sn + xo * cs;
    }
}

/* plain rmsnorm: g_hn = rms_norm(src, w) */
__global__ void k_rmsnorm(const float* __restrict__ src,
                          const float* __restrict__ w) {
    int row = blockIdx.x;
    __shared__ float red[256];
    const float* xp = src + (size_t)row * DM;
    float ss = 0.f;
    for (int d = threadIdx.x; d < DM; d += 256) { float v = xp[d]; ss += v * v; }
    red[threadIdx.x] = ss; __syncthreads();
    for (int st = 128; st > 0; st >>= 1) {
        if (threadIdx.x < st) red[threadIdx.x] += red[threadIdx.x + st];
        __syncthreads();
    }
    float inv = rsqrtf(red[0] / (float)DM + 1e-6f);
    float* op = g_hn + (size_t)row * DM;
    for (int d = threadIdx.x; d < DM; d += 256) op[d] = xp[d] * inv * w[d];
}

/* --------------------------- generic SGEMM core ----------------------------
   C[row0+r, n] = sum_k A[arow(r), k] * B[k, n]  (+bias) (+residual)
   A gathered through rowmap when provided; per-expert segments via segoff.
   BM=128, BN=128, BK=8, 256 threads, 8x8 per-thread microtile.              */
__global__ void __launch_bounds__(256)
k_gemm(const float* __restrict__ A, int lda,
       const float* __restrict__ Bmat, long bstride,
       const float* __restrict__ bias, long biasStride,
       const float* __restrict__ resid,
       float* __restrict__ C, int ldc,
       int M, int N, int K,
       const int* __restrict__ segoff,
       const int* __restrict__ rowmap) {
    int e = blockIdx.z;
    int row0 = 0, rows = M;
    if (segoff) { row0 = segoff[e]; rows = segoff[e + 1] - row0; }
    int mBase = blockIdx.y * 128;
    if (mBase >= rows) return;
    const float* B  = Bmat + (long)e * bstride;
    const float* bi = bias ? (bias + (long)e * biasStride) : (const float*)0;
    int nBase = blockIdx.x * 128;

    __shared__ float As[8][128];
    __shared__ float Bs[8][128];
    int tid  = threadIdx.x;
    int arow = tid >> 1, acol = (tid & 1) * 4;     /* A tile: 128 x 8 */
    int brow = tid >> 5, bcol = (tid & 31) * 4;    /* B tile: 8 x 128 */
    int ty = tid >> 4, tx = tid & 15;

    float acc[8][8];
#pragma unroll
    for (int i = 0; i < 8; i++)
#pragma unroll
        for (int j = 0; j < 8; j++) acc[i][j] = 0.f;

    int  aRowL  = mBase + arow;                    /* local row in segment */
    bool aValid = aRowL < rows;
    long aSrc   = 0;
    if (aValid) aSrc = rowmap ? (long)rowmap[row0 + aRowL] : (long)(row0 + aRowL);
    const float* Aptr = A + aSrc * (long)lda + acol;
    const float* Bptr = B + (long)brow * N + nBase + bcol;

    for (int k0 = 0; k0 < K; k0 += 8) {
        float4 av = aValid ? *(const float4*)(Aptr + k0)
                           : make_float4(0.f, 0.f, 0.f, 0.f);
        float4 bv = *(const float4*)(Bptr + (long)k0 * N);
        As[acol + 0][arow] = av.x;
        As[acol + 1][arow] = av.y;
        As[acol + 2][arow] = av.z;
        As[acol + 3][arow] = av.w;
        *(float4*)&Bs[brow][bcol] = bv;
        __syncthreads();
#pragma unroll
        for (int kk = 0; kk < 8; kk++) {
            float a[8], b[8];
#pragma unroll
            for (int i = 0; i < 8; i++) a[i] = As[kk][ty * 8 + i];
#pragma unroll
            for (int j = 0; j < 8; j++) b[j] = Bs[kk][tx * 8 + j];
#pragma unroll
            for (int i = 0; i < 8; i++)
#pragma unroll
                for (int j = 0; j < 8; j++) acc[i][j] += a[i] * b[j];
        }
        __syncthreads();
    }

#pragma unroll
    for (int i = 0; i < 8; i++) {
        int r = mBase + ty * 8 + i;
        if (r >= rows) continue;
        long cRow = row0 + r;
#pragma unroll
        for (int j = 0; j < 8; j++) {
            int col = nBase + tx * 8 + j;
            float v = acc[i][j];
            if (bi)    v += bi[col];
            if (resid) v += resid[cRow * (long)ldc + col];
            C[cRow * (long)ldc + col] = v;
        }
    }
}

/* ------------------------- flash-style attention --------------------------
   One thread per query row (128 q-rows per CTA), online softmax, key tiles
   of 64 staged in smem, inner chunks of 32 scores in registers.            */
__global__ void __launch_bounds__(128)
k_attn() {
    int qt = blockIdx.x;            /* 0..7  (q tile of 128)  */
    int h  = blockIdx.y;            /* 0..15 head             */
    int b  = blockIdx.z;            /* 0..1  batch            */
    int g  = h / HPG;               /* kv group               */
    int i  = qt * 128 + threadIdx.x;

    __shared__ float Ks[64][DK];
    __shared__ float Vs[64][DK];

    float q[DK];
    const float* qp = g_q + ((size_t)(b * SEQ + i)) * DM + h * DK;
#pragma unroll
    for (int d = 0; d < DK; d++) q[d] = qp[d] * 0.125f;   /* 1/sqrt(64) */

    float o[DK];
#pragma unroll
    for (int d = 0; d < DK; d++) o[d] = 0.f;
    float m = -1e30f, l = 0.f;

    int ktmax = (qt * 128 + 127) / 64;
    for (int kt = 0; kt <= ktmax; kt++) {
        int j0 = kt * 64;
        __syncthreads();
        for (int t = threadIdx.x; t < 64 * DK; t += 128) {
            int jj = t / DK, d = t % DK;
            size_t src = ((size_t)(b * SEQ + j0 + jj)) * (NG * DK) + g * DK + d;
            Ks[jj][d] = g_k[src];
            Vs[jj][d] = g_v[src];
        }
        __syncthreads();

        for (int c0 = 0; c0 < 64; c0 += 32) {
            float s[32];
            for (int jj = 0; jj < 32; jj++) {
                float acc = 0.f;
#pragma unroll
                for (int d = 0; d < DK; d++) acc += q[d] * Ks[c0 + jj][d];
                s[jj] = (j0 + c0 + jj <= i) ? acc : -1e30f;
            }
            float mn = m;
            for (int jj = 0; jj < 32; jj++) mn = fmaxf(mn, s[jj]);
            float scale = expf(m - mn);
            m = mn;
            l *= scale;
#pragma unroll
            for (int d = 0; d < DK; d++) o[d] *= scale;
            for (int jj = 0; jj < 32; jj++) {
                float p = (j0 + c0 + jj <= i) ? expf(s[jj] - mn) : 0.f;
                l += p;
#pragma unroll
                for (int d = 0; d < DK; d++) o[d] += p * Vs[c0 + jj][d];
            }
        }
    }

    float invl = 1.f / l;
    float* op = g_attn + ((size_t)(b * SEQ + i)) * DM + h * DK;
#pragma unroll
    for (int d = 0; d < DK; d++) op[d] = o[d] * invl;
}

/* ------------------------------- MoE routing ------------------------------ */

__global__ void k_router(const float* __restrict__ rw,
                         const float* __restrict__ rb) {
    int t    = blockIdx.x * 8 + (threadIdx.x >> 5);
    int lane = threadIdx.x & 31;
    float part[NE];
#pragma unroll
    for (int e = 0; e < NE; e++) part[e] = 0.f;
    const float* hp = g_hn + (size_t)t * DM;
    for (int d = lane; d < DM; d += 32) {
        float hv = hp[d];
        const float* rp = rw + (size_t)d * NE;
#pragma unroll
        for (int e = 0; e < NE; e++) part[e] += hv * rp[e];
    }
#pragma unroll
    for (int e = 0; e < NE; e++)
        for (int off = 16; off > 0; off >>= 1)
            part[e] += __shfl_xor_sync(0xffffffffu, part[e], off);
    if (lane == 0) {
        float lg[NE];
#pragma unroll
        for (int e = 0; e < NE; e++) lg[e] = part[e] + rb[e];
        int i0 = 0;
        for (int e = 1; e < NE; e++) if (lg[e] > lg[i0]) i0 = e;
        int i1 = (i0 == 0) ? 1 : 0;
        for (int e = 0; e < NE; e++)
            if (e != i0 && lg[e] > lg[i1]) i1 = e;
        float e1 = expf(lg[i1] - lg[i0]);   /* lg[i0] >= lg[i1] */
        float inv = 1.f / (1.f + e1);
        g_tidx[t * 2 + 0] = i0; g_tidx[t * 2 + 1] = i1;
        g_twgt[t * 2 + 0] = inv; g_twgt[t * 2 + 1] = e1 * inv;
        atomicAdd(&g_cnt[i0], 1);
        atomicAdd(&g_cnt[i1], 1);
    }
}

__global__ void k_scan() {
    if (threadIdx.x == 0) {
        int acc = 0;
        for (int e = 0; e < NE; e++) {
            g_off[e] = acc; acc += g_cnt[e]; g_cur[e] = 0;
        }
        g_off[NE] = acc;   /* == NASSIGN */
    }
}

__global__ void k_scatter() {
    int t = blockIdx.x * 256 + threadIdx.x;
    if (t >= NTOK) return;
#pragma unroll
    for (int k = 0; k < 2; k++) {
        int e = g_tidx[t * 2 + k];
        int p = atomicAdd(&g_cur[e], 1);
        int row = g_off[e] + p;
        g_tok[row] = t;
        g_trow[t * 2 + k] = row;
    }
}

/* h = h2 * silu(h1), in place into g_h1. Covers all NASSIGN*DFF elements. */
__global__ void k_silu() {
    size_t i = ((size_t)blockIdx.x * 256 + threadIdx.x) * 4;
    float4 a = *(float4*)&g_h1[i];
    float4 b = *(float4*)&g_h2[i];
    a.x = b.x * a.x / (1.f + expf(-a.x));
    a.y = b.y * a.y / (1.f + expf(-a.y));
    a.z = b.z * a.z / (1.f + expf(-a.z));
    a.w = b.w * a.w / (1.f + expf(-a.w));
    *(float4*)&g_h1[i] = a;
}

/* out[t] += w0*eo[row0(t)] + w1*eo[row1(t)] */
__global__ void k_combine(float* __restrict__ out) {
    int t = blockIdx.x;
    int   r0 = g_trow[t * 2],     r1 = g_trow[t * 2 + 1];
    float w0 = g_twgt[t * 2],     w1 = g_twgt[t * 2 + 1];
    const float* e0 = g_eo + (size_t)r0 * DM;
    const float* e1 = g_eo + (size_t)r1 * DM;
    float* op = out + (size_t)t * DM;
    for (int d = threadIdx.x; d < DM; d += 256)
        op[d] += w0 * e0[d] + w1 * e1[d];
}

/* --------------------------------- driver --------------------------------- */

extern "C" void kernel_launch(void* const* d_in, const int* in_sizes, int n_in,
                              void* d_out, int out_size) {
    const float* x   = (const float*)d_in[0];
    const float* n1w = (const float*)d_in[1];
    const float* Wq  = (const float*)d_in[2];
    const float* Wk  = (const float*)d_in[3];
    const float* Wv  = (const float*)d_in[4];
    const float* Wo  = (const float*)d_in[5];
    const float* n2w = (const float*)d_in[6];
    const float* rw  = (const float*)d_in[7];
    const float* rb  = (const float*)d_in[8];
    const float* W1  = (const float*)d_in[9];
    const float* b1  = (const float*)d_in[10];
    const float* W2  = (const float*)d_in[11];
    const float* b2  = (const float*)d_in[12];
    const float* W3  = (const float*)d_in[13];
    const float* b3  = (const float*)d_in[14];
    float* out = (float*)d_out;

    void *p_xr, *p_q, *p_k, *p_v, *p_attn, *p_hn, *p_h1, *p_h2, *p_eo, *p_off, *p_tok;
    cudaGetSymbolAddress(&p_xr,  g_xr);
    cudaGetSymbolAddress(&p_q,   g_q);
    cudaGetSymbolAddress(&p_k,   g_k);
    cudaGetSymbolAddress(&p_v,   g_v);
    cudaGetSymbolAddress(&p_attn,g_attn);
    cudaGetSymbolAddress(&p_hn,  g_hn);
    cudaGetSymbolAddress(&p_h1,  g_h1);
    cudaGetSymbolAddress(&p_h2,  g_h2);
    cudaGetSymbolAddress(&p_eo,  g_eo);
    cudaGetSymbolAddress(&p_off, g_off);
    cudaGetSymbolAddress(&p_tok, g_tok);
    float* xr   = (float*)p_xr;
    float* qb   = (float*)p_q;
    float* kb   = (float*)p_k;
    float* vb   = (float*)p_v;
    float* attn = (float*)p_attn;
    float* hn   = (float*)p_hn;
    float* h1b  = (float*)p_h1;
    float* h2b  = (float*)p_h2;
    float* eob  = (float*)p_eo;
    int*   offp = (int*)p_off;
    int*   tokp = (int*)p_tok;

    /* 0: reset per-replay state */
    k_zero<<<1, 32>>>();

    /* 1: xn = rmsnorm(x); xr = rope(xn) */
    k_norm_rope<<<NTOK, 256>>>(x, n1w);

    /* 2: Q/K/V projections */
    k_gemm<<<dim3(DM/128, NTOK/128, 1), 256>>>(xr, DM, Wq, 0, 0, 0, 0,
                                               qb, DM, NTOK, DM, DM, 0, 0);
    k_gemm<<<dim3((NG*DK)/128, NTOK/128, 1), 256>>>(xr, DM, Wk, 0, 0, 0, 0,
                                               kb, NG*DK, NTOK, NG*DK, DM, 0, 0);
    k_gemm<<<dim3((NG*DK)/128, NTOK/128, 1), 256>>>(xr, DM, Wv, 0, 0, 0, 0,
                                               vb, NG*DK, NTOK, NG*DK, DM, 0, 0);

    /* 3: causal GQA attention */
    k_attn<<<dim3(SEQ/128, NH, BATCH), 128>>>();

    /* 4: out = x + attn @ Wo   (residual 1; out doubles as h) */
    k_gemm<<<dim3(DM/128, NTOK/128, 1), 256>>>(attn, DM, Wo, 0, 0, 0, x,
                                               out, DM, NTOK, DM, DM, 0, 0);

    /* 5: hn = rmsnorm(h) */
    k_rmsnorm<<<NTOK, 256>>>(out, n2w);

    /* 6: router + top2 + bucket by expert */
    k_router<<<NTOK/8, 256>>>(rw, rb);
    k_scan<<<1, 32>>>();
    k_scatter<<<NTOK/256, 256>>>();

    /* 7: expert FFN (grouped GEMMs over per-expert segments) */
    k_gemm<<<dim3(DFF/128, NTOK/128, NE), 256>>>(hn, DM, W1, (long)DM*DFF,
                                                 b1, DFF, 0,
                                                 h1b, DFF, 0, DFF, DM,
                                                 offp, tokp);
    k_gemm<<<dim3(DFF/128, NTOK/128, NE), 256>>>(hn, DM, W2, (long)DM*DFF,
                                                 b2, DFF, 0,
                                                 h2b, DFF, 0, DFF, DM,
                                                 offp, tokp);
    k_silu<<<(NASSIGN*(DFF/4))/256, 256>>>();
    k_gemm<<<dim3(DM/128, NTOK/128, NE), 256>>>(h1b, DFF, W3, (long)DFF*DM,
                                                b3, DM, 0,
                                                eob, DM, 0, DM, DFF,
                                                offp, 0);

    /* 8: out += combine(top2 weights, expert outputs)  (residual 2) */
    k_combine<<<NTOK, 256>>>(out);
}

// round 6
// speedup vs baseline: 1.9887x; 1.9887x over previous
#include <cuda_runtime.h>
#include <stdint.h>
#include <math.h>

#define BATCH 2
#define SEQ   1024
#define DM    1024
#define NH    16
#define DK    64
#define NG    4
#define HPG   4
#define DFF   4096
#define NE    8
#define NTOK  (BATCH*SEQ)      /* 2048 */
#define NASSIGN (NTOK*2)       /* 4096 */

/* ------------------------- scratch (device globals) ------------------------ */
__device__ float g_xr[NTOK*DM];
__device__ float g_q [NTOK*DM];
__device__ float g_k [NTOK*NG*DK];
__device__ float g_v [NTOK*NG*DK];
__device__ float g_attn[NTOK*DM];
__device__ float g_hn[NTOK*DM];
__device__ float g_h1[(size_t)NASSIGN*DFF];
__device__ float g_h2[(size_t)NASSIGN*DFF];
__device__ float g_eo[NASSIGN*DM];
__device__ int   g_cnt[NE];
__device__ int   g_off[NE+1];
__device__ int   g_cur[NE];
__device__ int   g_tok[NASSIGN];
__device__ int   g_tidx[NTOK*2];
__device__ float g_twgt[NTOK*2];
__device__ int   g_trow[NTOK*2];

/* ------------------------------ helpers ----------------------------------- */

__device__ __forceinline__ uint32_t f2tf(float x){
    uint32_t r; asm("cvt.rna.tf32.f32 %0, %1;" : "=r"(r) : "f"(x)); return r;
}

__device__ __forceinline__ void mma16n8k8(float* c, const uint32_t* a,
                                          const uint32_t* b){
    asm("mma.sync.aligned.m16n8k8.row.col.f32.tf32.tf32.f32 "
        "{%0,%1,%2,%3}, {%4,%5,%6,%7}, {%8,%9}, {%0,%1,%2,%3};"
        : "+f"(c[0]), "+f"(c[1]), "+f"(c[2]), "+f"(c[3])
        : "r"(a[0]), "r"(a[1]), "r"(a[2]), "r"(a[3]),
          "r"(b[0]), "r"(b[1]));
}

/* ------------------------------ small kernels ------------------------------ */

__global__ void k_zero() {
    if (threadIdx.x < NE) g_cnt[threadIdx.x] = 0;
}

__global__ void k_norm_rope(const float* __restrict__ x,
                            const float* __restrict__ w) {
    int row = blockIdx.x;
    int s   = row % SEQ;
    __shared__ float xs[DM];
    __shared__ float red[256];
    const float* xp = x + (size_t)row * DM;
    float ss = 0.f;
    for (int d = threadIdx.x; d < DM; d += 256) {
        float v = xp[d]; xs[d] = v; ss += v * v;
    }
    red[threadIdx.x] = ss; __syncthreads();
    for (int st = 128; st > 0; st >>= 1) {
        if (threadIdx.x < st) red[threadIdx.x] += red[threadIdx.x + st];
        __syncthreads();
    }
    float inv = rsqrtf(red[0] / (float)DM + 1e-6f);
    float* op = g_xr + (size_t)row * DM;
    for (int k = threadIdx.x; k < DM / 2; k += 256) {
        float theta = powf(10000.f, -(float)k / (float)(DM / 2));
        float ang = (float)s * theta;
        float sn, cs; sincosf(ang, &sn, &cs);
        float xe = xs[2 * k]     * inv * w[2 * k];
        float xo = xs[2 * k + 1] * inv * w[2 * k + 1];
        op[k]          = xe * cs - xo * sn;
        op[DM / 2 + k] = xe * sn + xo * cs;
    }
}

__global__ void k_rmsnorm(const float* __restrict__ src,
                          const float* __restrict__ w) {
    int row = blockIdx.x;
    __shared__ float red[256];
    const float* xp = src + (size_t)row * DM;
    float ss = 0.f;
    for (int d = threadIdx.x; d < DM; d += 256) { float v = xp[d]; ss += v * v; }
    red[threadIdx.x] = ss; __syncthreads();
    for (int st = 128; st > 0; st >>= 1) {
        if (threadIdx.x < st) red[threadIdx.x] += red[threadIdx.x + st];
        __syncthreads();
    }
    float inv = rsqrtf(red[0] / (float)DM + 1e-6f);
    float* op = g_hn + (size_t)row * DM;
    for (int d = threadIdx.x; d < DM; d += 256) op[d] = xp[d] * inv * w[d];
}

/* ------------------- warp-MMA tf32 GEMM (128x128 tile) ---------------------
   C[row0+r, nBase+c] = sum_k A[arow(r), k] * B[k, n]  (+bias)(+resid)
   BK=32, double-buffered smem. A transposed to [k][m] (stride 132),
   B natural [k][n] (stride 132) — both conflict-free for frag loads.
   8 warps: warp_m = wid&1 (64 rows), warp_n = wid>>1 (32 cols).
   Per warp: 4 m-tiles x 4 n-tiles of m16n8k8 tf32 mma.sync.                 */
#define SA 132
#define TG_SMEM (4*32*SA*4)     /* 2 bufs x (A + B) x 32 rows x SA floats */

__global__ void __launch_bounds__(256)
k_tgemm(const float* __restrict__ A, int lda,
        const float* __restrict__ Bmat, long bstride,
        const float* __restrict__ bias, long biasStride,
        const float* __restrict__ resid,
        float* __restrict__ C, int ldc,
        int M, int N, int K,
        const int* __restrict__ segoff,
        const int* __restrict__ rowmap) {
    extern __shared__ float sm[];

    int e = blockIdx.z;
    int row0 = 0, rows = M;
    if (segoff) { row0 = segoff[e]; rows = segoff[e + 1] - row0; }
    int mBase = blockIdx.y * 128;
    if (mBase >= rows) return;
    int nBase = blockIdx.x * 128;
    const float* Bp = Bmat + (long)e * bstride;
    const float* bi = bias ? (bias + (long)e * biasStride) : (const float*)0;

    int tid  = threadIdx.x;
    int wid  = tid >> 5, lane = tid & 31;
    int g = lane >> 2, t = lane & 3;
    int warp_m = wid & 1, warp_n = wid >> 1;

    /* A loader mapping: each thread owns one gathered row, 4 float4 per chunk */
    int  mloc  = tid & 127;
    int  ak4   = (tid >> 7) * 4;           /* 0 or 4 */
    bool aValid = (mBase + mloc) < rows;
    long aSrc = 0;
    if (aValid) aSrc = rowmap ? (long)rowmap[row0 + mBase + mloc]
                              : (long)(row0 + mBase + mloc);
    const float* Ap = A + aSrc * (long)lda;

    /* B loader mapping: col4 fixed, 4 k rows per chunk */
    int bc4  = tid & 31;
    int bk   = tid >> 5;                    /* 0..7 */
    const float* Bq = Bp + nBase + bc4 * 4;

    float* AsB = sm;                        /* 2 x 32 x SA */
    float* BsB = sm + 2 * 32 * SA;          /* 2 x 32 x SA */

    float acc[4][4][4];
#pragma unroll
    for (int i = 0; i < 4; i++)
#pragma unroll
        for (int j = 0; j < 4; j++)
#pragma unroll
            for (int q = 0; q < 4; q++) acc[i][j][q] = 0.f;

    int nCh = K >> 5;

    float4 av[4], bv[4];
    /* prologue: load chunk 0 */
#pragma unroll
    for (int j = 0; j < 4; j++) {
        int k = ak4 + 8 * j;
        av[j] = aValid ? *(const float4*)(Ap + k)
                       : make_float4(0.f, 0.f, 0.f, 0.f);
        bv[j] = *(const float4*)(Bq + (long)(bk + 8 * j) * N);
    }
    {
        float* As = AsB; float* Bs = BsB;
#pragma unroll
        for (int j = 0; j < 4; j++) {
            int k = ak4 + 8 * j;
            As[(k+0)*SA + mloc] = __uint_as_float(f2tf(av[j].x));
            As[(k+1)*SA + mloc] = __uint_as_float(f2tf(av[j].y));
            As[(k+2)*SA + mloc] = __uint_as_float(f2tf(av[j].z));
            As[(k+3)*SA + mloc] = __uint_as_float(f2tf(av[j].w));
            uint4 u;
            u.x = f2tf(bv[j].x); u.y = f2tf(bv[j].y);
            u.z = f2tf(bv[j].z); u.w = f2tf(bv[j].w);
            *(uint4*)&Bs[(bk + 8*j)*SA + bc4*4] = u;
        }
    }
    __syncthreads();

    for (int kc = 0; kc < nCh; kc++) {
        if (kc + 1 < nCh) {
            long kg = (long)(kc + 1) * 32;
#pragma unroll
            for (int j = 0; j < 4; j++) {
                int k = ak4 + 8 * j;
                av[j] = aValid ? *(const float4*)(Ap + kg + k)
                               : make_float4(0.f, 0.f, 0.f, 0.f);
                bv[j] = *(const float4*)(Bq + (kg + bk + 8 * j) * N);
            }
        }

        const uint32_t* As = (const uint32_t*)(AsB + (kc & 1) * 32 * SA);
        const uint32_t* Bs = (const uint32_t*)(BsB + (kc & 1) * 32 * SA);
#pragma unroll
        for (int ks = 0; ks < 4; ks++) {
            int kb = ks * 8;
            uint32_t ar[4][4], br[4][2];
#pragma unroll
            for (int mt = 0; mt < 4; mt++) {
                int m = warp_m * 64 + mt * 16 + g;
                ar[mt][0] = As[(kb + t)    *SA + m];
                ar[mt][1] = As[(kb + t)    *SA + m + 8];
                ar[mt][2] = As[(kb + t + 4)*SA + m];
                ar[mt][3] = As[(kb + t + 4)*SA + m + 8];
            }
#pragma unroll
            for (int nt = 0; nt < 4; nt++) {
                int n = warp_n * 32 + nt * 8 + g;
                br[nt][0] = Bs[(kb + t)    *SA + n];
                br[nt][1] = Bs[(kb + t + 4)*SA + n];
            }
#pragma unroll
            for (int mt = 0; mt < 4; mt++)
#pragma unroll
                for (int nt = 0; nt < 4; nt++)
                    mma16n8k8(acc[mt][nt], ar[mt], br[nt]);
        }

        if (kc + 1 < nCh) {
            float* Asw = AsB + ((kc + 1) & 1) * 32 * SA;
            float* Bsw = BsB + ((kc + 1) & 1) * 32 * SA;
#pragma unroll
            for (int j = 0; j < 4; j++) {
                int k = ak4 + 8 * j;
                Asw[(k+0)*SA + mloc] = __uint_as_float(f2tf(av[j].x));
                Asw[(k+1)*SA + mloc] = __uint_as_float(f2tf(av[j].y));
                Asw[(k+2)*SA + mloc] = __uint_as_float(f2tf(av[j].z));
                Asw[(k+3)*SA + mloc] = __uint_as_float(f2tf(av[j].w));
                uint4 u;
                u.x = f2tf(bv[j].x); u.y = f2tf(bv[j].y);
                u.z = f2tf(bv[j].z); u.w = f2tf(bv[j].w);
                *(uint4*)&Bsw[(bk + 8*j)*SA + bc4*4] = u;
            }
            __syncthreads();
        }
    }

    /* epilogue */
#pragma unroll
    for (int mt = 0; mt < 4; mt++) {
        int rl0 = mBase + warp_m * 64 + mt * 16 + g;
#pragma unroll
        for (int half = 0; half < 2; half++) {
            int rl = rl0 + half * 8;
            if (rl >= rows) continue;
            long cRow = row0 + rl;
            float* Crow = C + cRow * (long)ldc;
            const float* Rrow = resid ? (resid + cRow * (long)ldc) : (const float*)0;
#pragma unroll
            for (int nt = 0; nt < 4; nt++) {
                int c = nBase + warp_n * 32 + nt * 8 + 2 * t;
                float v0 = acc[mt][nt][half * 2 + 0];
                float v1 = acc[mt][nt][half * 2 + 1];
                if (bi)   { v0 += bi[c];   v1 += bi[c + 1]; }
                if (Rrow) { v0 += Rrow[c]; v1 += Rrow[c + 1]; }
                float2 o = make_float2(v0, v1);
                *(float2*)(Crow + c) = o;
            }
        }
    }
}

/* ------------------------- flash-style attention -------------------------- */
__global__ void __launch_bounds__(128)
k_attn() {
    int qt = blockIdx.x;
    int h  = blockIdx.y;
    int b  = blockIdx.z;
    int g  = h / HPG;
    int i  = qt * 128 + threadIdx.x;

    __shared__ float Ks[64][DK];
    __shared__ float Vs[64][DK];

    float q[DK];
    const float* qp = g_q + ((size_t)(b * SEQ + i)) * DM + h * DK;
#pragma unroll
    for (int d = 0; d < DK; d++) q[d] = qp[d] * 0.125f;

    float o[DK];
#pragma unroll
    for (int d = 0; d < DK; d++) o[d] = 0.f;
    float m = -1e30f, l = 0.f;

    int ktmax = (qt * 128 + 127) / 64;
    for (int kt = 0; kt <= ktmax; kt++) {
        int j0 = kt * 64;
        __syncthreads();
        for (int tt = threadIdx.x; tt < 64 * DK; tt += 128) {
            int jj = tt / DK, d = tt % DK;
            size_t src = ((size_t)(b * SEQ + j0 + jj)) * (NG * DK) + g * DK + d;
            Ks[jj][d] = g_k[src];
            Vs[jj][d] = g_v[src];
        }
        __syncthreads();

        for (int c0 = 0; c0 < 64; c0 += 32) {
            float s[32];
            for (int jj = 0; jj < 32; jj++) {
                float acc = 0.f;
#pragma unroll
                for (int d = 0; d < DK; d++) acc += q[d] * Ks[c0 + jj][d];
                s[jj] = (j0 + c0 + jj <= i) ? acc : -1e30f;
            }
            float mn = m;
            for (int jj = 0; jj < 32; jj++) mn = fmaxf(mn, s[jj]);
            float scale = expf(m - mn);
            m = mn;
            l *= scale;
#pragma unroll
            for (int d = 0; d < DK; d++) o[d] *= scale;
            for (int jj = 0; jj < 32; jj++) {
                float p = (j0 + c0 + jj <= i) ? expf(s[jj] - mn) : 0.f;
                l += p;
#pragma unroll
                for (int d = 0; d < DK; d++) o[d] += p * Vs[c0 + jj][d];
            }
        }
    }

    float invl = 1.f / l;
    float* op = g_attn + ((size_t)(b * SEQ + i)) * DM + h * DK;
#pragma unroll
    for (int d = 0; d < DK; d++) op[d] = o[d] * invl;
}

/* ------------------------------- MoE routing ------------------------------ */

__global__ void k_router(const float* __restrict__ rw,
                         const float* __restrict__ rb) {
    int t    = blockIdx.x * 8 + (threadIdx.x >> 5);
    int lane = threadIdx.x & 31;
    float part[NE];
#pragma unroll
    for (int e = 0; e < NE; e++) part[e] = 0.f;
    const float* hp = g_hn + (size_t)t * DM;
    for (int d = lane; d < DM; d += 32) {
        float hv = hp[d];
        const float* rp = rw + (size_t)d * NE;
#pragma unroll
        for (int e = 0; e < NE; e++) part[e] += hv * rp[e];
    }
#pragma unroll
    for (int e = 0; e < NE; e++)
        for (int off = 16; off > 0; off >>= 1)
            part[e] += __shfl_xor_sync(0xffffffffu, part[e], off);
    if (lane == 0) {
        float lg[NE];
#pragma unroll
        for (int e = 0; e < NE; e++) lg[e] = part[e] + rb[e];
        int i0 = 0;
        for (int e = 1; e < NE; e++) if (lg[e] > lg[i0]) i0 = e;
        int i1 = (i0 == 0) ? 1 : 0;
        for (int e = 0; e < NE; e++)
            if (e != i0 && lg[e] > lg[i1]) i1 = e;
        float e1 = expf(lg[i1] - lg[i0]);
        float inv = 1.f / (1.f + e1);
        g_tidx[t * 2 + 0] = i0; g_tidx[t * 2 + 1] = i1;
        g_twgt[t * 2 + 0] = inv; g_twgt[t * 2 + 1] = e1 * inv;
        atomicAdd(&g_cnt[i0], 1);
        atomicAdd(&g_cnt[i1], 1);
    }
}

__global__ void k_scan() {
    if (threadIdx.x == 0) {
        int acc = 0;
        for (int e = 0; e < NE; e++) {
            g_off[e] = acc; acc += g_cnt[e]; g_cur[e] = 0;
        }
        g_off[NE] = acc;
    }
}

__global__ void k_scatter() {
    int t = blockIdx.x * 256 + threadIdx.x;
    if (t >= NTOK) return;
#pragma unroll
    for (int k = 0; k < 2; k++) {
        int e = g_tidx[t * 2 + k];
        int p = atomicAdd(&g_cur[e], 1);
        int row = g_off[e] + p;
        g_tok[row] = t;
        g_trow[t * 2 + k] = row;
    }
}

__global__ void k_silu() {
    size_t i = ((size_t)blockIdx.x * 256 + threadIdx.x) * 4;
    float4 a = *(float4*)&g_h1[i];
    float4 b = *(float4*)&g_h2[i];
    a.x = b.x * a.x / (1.f + expf(-a.x));
    a.y = b.y * a.y / (1.f + expf(-a.y));
    a.z = b.z * a.z / (1.f + expf(-a.z));
    a.w = b.w * a.w / (1.f + expf(-a.w));
    *(float4*)&g_h1[i] = a;
}

__global__ void k_combine(float* __restrict__ out) {
    int t = blockIdx.x;
    int   r0 = g_trow[t * 2],     r1 = g_trow[t * 2 + 1];
    float w0 = g_twgt[t * 2],     w1 = g_twgt[t * 2 + 1];
    const float* e0 = g_eo + (size_t)r0 * DM;
    const float* e1 = g_eo + (size_t)r1 * DM;
    float* op = out + (size_t)t * DM;
    for (int d = threadIdx.x; d < DM; d += 256)
        op[d] += w0 * e0[d] + w1 * e1[d];
}

/* --------------------------------- driver --------------------------------- */

extern "C" void kernel_launch(void* const* d_in, const int* in_sizes, int n_in,
                              void* d_out, int out_size) {
    const float* x   = (const float*)d_in[0];
    const float* n1w = (const float*)d_in[1];
    const float* Wq  = (const float*)d_in[2];
    const float* Wk  = (const float*)d_in[3];
    const float* Wv  = (const float*)d_in[4];
    const float* Wo  = (const float*)d_in[5];
    const float* n2w = (const float*)d_in[6];
    const float* rw  = (const float*)d_in[7];
    const float* rb  = (const float*)d_in[8];
    const float* W1  = (const float*)d_in[9];
    const float* b1  = (const float*)d_in[10];
    const float* W2  = (const float*)d_in[11];
    const float* b2  = (const float*)d_in[12];
    const float* W3  = (const float*)d_in[13];
    const float* b3  = (const float*)d_in[14];
    float* out = (float*)d_out;

    cudaFuncSetAttribute(k_tgemm, cudaFuncAttributeMaxDynamicSharedMemorySize,
                         TG_SMEM);

    void *p_xr, *p_q, *p_k, *p_v, *p_attn, *p_hn, *p_h1, *p_h2, *p_eo, *p_off, *p_tok;
    cudaGetSymbolAddress(&p_xr,  g_xr);
    cudaGetSymbolAddress(&p_q,   g_q);
    cudaGetSymbolAddress(&p_k,   g_k);
    cudaGetSymbolAddress(&p_v,   g_v);
    cudaGetSymbolAddress(&p_attn,g_attn);
    cudaGetSymbolAddress(&p_hn,  g_hn);
    cudaGetSymbolAddress(&p_h1,  g_h1);
    cudaGetSymbolAddress(&p_h2,  g_h2);
    cudaGetSymbolAddress(&p_eo,  g_eo);
    cudaGetSymbolAddress(&p_off, g_off);
    cudaGetSymbolAddress(&p_tok, g_tok);
    float* xr   = (float*)p_xr;
    float* qb   = (float*)p_q;
    float* kb   = (float*)p_k;
    float* vb   = (float*)p_v;
    float* attn = (float*)p_attn;
    float* hn   = (float*)p_hn;
    float* h1b  = (float*)p_h1;
    float* h2b  = (float*)p_h2;
    float* eob  = (float*)p_eo;
    int*   offp = (int*)p_off;
    int*   tokp = (int*)p_tok;

    k_zero<<<1, 32>>>();
    k_norm_rope<<<NTOK, 256>>>(x, n1w);

    /* QKV projections (tf32 warp-mma path) */
    k_tgemm<<<dim3(DM/128, NTOK/128, 1), 256, TG_SMEM>>>(
        xr, DM, Wq, 0, 0, 0, 0, qb, DM, NTOK, DM, DM, 0, 0);
    k_tgemm<<<dim3((NG*DK)/128, NTOK/128, 1), 256, TG_SMEM>>>(
        xr, DM, Wk, 0, 0, 0, 0, kb, NG*DK, NTOK, NG*DK, DM, 0, 0);
    k_tgemm<<<dim3((NG*DK)/128, NTOK/128, 1), 256, TG_SMEM>>>(
        xr, DM, Wv, 0, 0, 0, 0, vb, NG*DK, NTOK, NG*DK, DM, 0, 0);

    k_attn<<<dim3(SEQ/128, NH, BATCH), 128>>>();

    /* out = x + attn @ Wo */
    k_tgemm<<<dim3(DM/128, NTOK/128, 1), 256, TG_SMEM>>>(
        attn, DM, Wo, 0, 0, 0, x, out, DM, NTOK, DM, DM, 0, 0);

    k_rmsnorm<<<NTOK, 256>>>(out, n2w);

    k_router<<<NTOK/8, 256>>>(rw, rb);
    k_scan<<<1, 32>>>();
    k_scatter<<<NTOK/256, 256>>>();

    /* expert FFN */
    k_tgemm<<<dim3(DFF/128, NTOK/128, NE), 256, TG_SMEM>>>(
        hn, DM, W1, (long)DM*DFF, b1, DFF, 0,
        h1b, DFF, 0, DFF, DM, offp, tokp);
    k_tgemm<<<dim3(DFF/128, NTOK/128, NE), 256, TG_SMEM>>>(
        hn, DM, W2, (long)DM*DFF, b2, DFF, 0,
        h2b, DFF, 0, DFF, DM, offp, tokp);
    k_silu<<<(NASSIGN*(DFF/4))/256, 256>>>();
    k_tgemm<<<dim3(DM/128, NTOK/128, NE), 256, TG_SMEM>>>(
        h1b, DFF, W3, (long)DFF*DM, b3, DM, 0,
        eob, DM, 0, DM, DFF, offp, 0);

    k_combine<<<NTOK, 256>>>(out);
}

// round 7
// speedup vs baseline: 2.8266x; 1.4213x over previous
#include <cuda_runtime.h>
#include <stdint.h>
#include <math.h>

#define BATCH 2
#define SEQ   1024
#define DM    1024
#define NH    16
#define DK    64
#define NG    4
#define HPG   4
#define DFF   4096
#define NE    8
#define NTOK  (BATCH*SEQ)      /* 2048 */
#define NASSIGN (NTOK*2)       /* 4096 */

/* ------------------------- scratch (device globals) ------------------------ */
__device__ float g_xr[NTOK*DM];
__device__ float g_q [NTOK*DM];
__device__ float g_k [NTOK*NG*DK];
__device__ float g_v [NTOK*NG*DK];
__device__ float g_attn[NTOK*DM];
__device__ float g_hn[NTOK*DM];
__device__ float g_h1[(size_t)NASSIGN*DFF];
__device__ float g_h2[(size_t)NASSIGN*DFF];
__device__ float g_eo[NASSIGN*DM];
__device__ int   g_cnt[NE];
__device__ int   g_off[NE+1];
__device__ int   g_cur[NE];
__device__ int   g_tok[NASSIGN];
__device__ int   g_tidx[NTOK*2];
__device__ float g_twgt[NTOK*2];
__device__ int   g_trow[NTOK*2];

/* ------------------------------ helpers ----------------------------------- */

__device__ __forceinline__ uint32_t f2tf(float x){
    uint32_t r; asm("cvt.rna.tf32.f32 %0, %1;" : "=r"(r) : "f"(x)); return r;
}
__device__ __forceinline__ uint32_t u2tf(uint32_t x){
    return f2tf(__uint_as_float(x));
}
__device__ __forceinline__ void mma16n8k8(float* c, const uint32_t* a,
                                          const uint32_t* b){
    asm("mma.sync.aligned.m16n8k8.row.col.f32.tf32.tf32.f32 "
        "{%0,%1,%2,%3}, {%4,%5,%6,%7}, {%8,%9}, {%0,%1,%2,%3};"
        : "+f"(c[0]), "+f"(c[1]), "+f"(c[2]), "+f"(c[3])
        : "r"(a[0]), "r"(a[1]), "r"(a[2]), "r"(a[3]),
          "r"(b[0]), "r"(b[1]));
}
__device__ __forceinline__ void ldsm4(uint32_t* r, uint32_t addr){
    asm("ldmatrix.sync.aligned.m8n8.x4.shared.b16 {%0,%1,%2,%3}, [%4];"
        : "=r"(r[0]), "=r"(r[1]), "=r"(r[2]), "=r"(r[3]) : "r"(addr));
}
__device__ __forceinline__ float ldsf(uint32_t a){
    float v; asm("ld.shared.f32 %0, [%1];" : "=f"(v) : "r"(a)); return v;
}
__device__ __forceinline__ void cpa16(uint32_t dst, const void* src, int sz){
    asm volatile("cp.async.cg.shared.global [%0], [%1], 16, %2;"
                 :: "r"(dst), "l"(src), "r"(sz));
}
__device__ __forceinline__ void cp_commit(){
    asm volatile("cp.async.commit_group;");
}
__device__ __forceinline__ void cp_wait1(){
    asm volatile("cp.async.wait_group 1;");
}

/* ------------------------------ small kernels ------------------------------ */

__global__ void k_zero() {
    if (threadIdx.x < NE) g_cnt[threadIdx.x] = 0;
}

__global__ void k_norm_rope(const float* __restrict__ x,
                            const float* __restrict__ w) {
    int row = blockIdx.x;
    int s   = row % SEQ;
    __shared__ float xs[DM];
    __shared__ float red[256];
    const float* xp = x + (size_t)row * DM;
    float ss = 0.f;
    for (int d = threadIdx.x; d < DM; d += 256) {
        float v = xp[d]; xs[d] = v; ss += v * v;
    }
    red[threadIdx.x] = ss; __syncthreads();
    for (int st = 128; st > 0; st >>= 1) {
        if (threadIdx.x < st) red[threadIdx.x] += red[threadIdx.x + st];
        __syncthreads();
    }
    float inv = rsqrtf(red[0] / (float)DM + 1e-6f);
    float* op = g_xr + (size_t)row * DM;
    for (int k = threadIdx.x; k < DM / 2; k += 256) {
        float theta = powf(10000.f, -(float)k / (float)(DM / 2));
        float ang = (float)s * theta;
        float sn, cs; sincosf(ang, &sn, &cs);
        float xe = xs[2 * k]     * inv * w[2 * k];
        float xo = xs[2 * k + 1] * inv * w[2 * k + 1];
        op[k]          = xe * cs - xo * sn;
        op[DM / 2 + k] = xe * sn + xo * cs;
    }
}

__global__ void k_rmsnorm(const float* __restrict__ src,
                          const float* __restrict__ w) {
    int row = blockIdx.x;
    __shared__ float red[256];
    const float* xp = src + (size_t)row * DM;
    float ss = 0.f;
    for (int d = threadIdx.x; d < DM; d += 256) { float v = xp[d]; ss += v * v; }
    red[threadIdx.x] = ss; __syncthreads();
    for (int st = 128; st > 0; st >>= 1) {
        if (threadIdx.x < st) red[threadIdx.x] += red[threadIdx.x + st];
        __syncthreads();
    }
    float inv = rsqrtf(red[0] / (float)DM + 1e-6f);
    float* op = g_hn + (size_t)row * DM;
    for (int d = threadIdx.x; d < DM; d += 256) op[d] = xp[d] * inv * w[d];
}

/* ------------- warp-MMA tf32 GEMM, cp.async 3-stage pipeline ---------------
   C[row0+r, n] = sum_k A[arow(r), k] * B[k, n]  (+bias)(+resid)
   BM=128 BN=128 BK=32, 256 thr, 8 warps (2m x 4n), warp tile 64x32.
   A smem [m][k] raw fp32, 144B rows  -> ldmatrix x4 fragments (+cvt).
   B smem [k][n] raw fp32, 528B rows  -> scalar LDS fragments (+cvt).       */
#define STAGES   3
#define A_STG    18432                 /* 128 rows x 144 B */
#define B_STG    16896                 /* 32 rows x 528 B  */
#define STG_B    (A_STG + B_STG)       /* 35328 */
#define TG_SMEM  (STAGES * STG_B)      /* 105984 */

__global__ void __launch_bounds__(256)
k_tgemm(const float* __restrict__ A, int lda,
        const float* __restrict__ Bmat, long bstride,
        const float* __restrict__ bias, long biasStride,
        const float* __restrict__ resid,
        float* __restrict__ C, int ldc,
        int M, int N, int K,
        const int* __restrict__ segoff,
        const int* __restrict__ rowmap) {
    extern __shared__ __align__(128) char smem[];

    int e = blockIdx.z;
    int row0 = 0, rows = M;
    if (segoff) { row0 = segoff[e]; rows = segoff[e + 1] - row0; }
    int mBase = blockIdx.y * 128;
    if (mBase >= rows) return;
    int nBase = blockIdx.x * 128;
    const float* Bp = Bmat + (long)e * bstride;
    const float* bi = bias ? (bias + (long)e * biasStride) : (const float*)0;

    uint32_t sbase = (uint32_t)__cvta_generic_to_shared(smem);
    int tid = threadIdx.x, lane = tid & 31, wid = tid >> 5;
    int g = lane >> 2, t = lane & 3;
    int warp_m = wid & 1, warp_n = wid >> 1;

    /* A copy plan: pass p handles row m = p*32 + (tid>>3), chunk col tid&7  */
    const float* srcA[4]; int szA[4]; uint32_t dstA[4];
    int ac = tid & 7;
#pragma unroll
    for (int p = 0; p < 4; p++) {
        int m  = p * 32 + (tid >> 3);
        int rl = mBase + m;
        bool v = rl < rows;
        long ai = 0;
        if (v) ai = rowmap ? (long)rowmap[row0 + rl] : (long)(row0 + rl);
        srcA[p] = A + ai * (long)lda + ac * 4;
        szA[p]  = v ? 16 : 0;
        dstA[p] = (uint32_t)(m * 144 + ac * 16);
    }
    /* B copy plan: row k = tid>>3, chunks (tid&7) + 8j                      */
    int bkr = tid >> 3;
    const float* srcB = Bp + (long)bkr * N + nBase + (tid & 7) * 4;
    uint32_t dstB = A_STG + (uint32_t)(bkr * 528 + (tid & 7) * 16);

    /* fragment address bases */
    uint32_t aRowOff = (uint32_t)((warp_m * 64 + (lane & 15)) * 144
                                  + ((lane >> 4) << 4));
    uint32_t bColOff = (uint32_t)(A_STG + (warp_n * 32 + g) * 4 + t * 528);

    float acc[4][4][4];
#pragma unroll
    for (int i = 0; i < 4; i++)
#pragma unroll
        for (int j = 0; j < 4; j++)
#pragma unroll
            for (int q = 0; q < 4; q++) acc[i][j][q] = 0.f;

    int nCh = K >> 5;

    /* prologue: issue STAGES-1 stages */
#pragma unroll
    for (int s = 0; s < STAGES - 1; s++) {
        if (s < nCh) {
            uint32_t sb = sbase + s * STG_B;
            long kB = (long)s * 32;
#pragma unroll
            for (int p = 0; p < 4; p++)
                cpa16(sb + dstA[p], srcA[p] + kB, szA[p]);
#pragma unroll
            for (int j = 0; j < 4; j++)
                cpa16(sb + dstB + j * 128, srcB + kB * N + j * 32, 16);
        }
        cp_commit();
    }

    for (int kc = 0; kc < nCh; kc++) {
        cp_wait1();
        __syncthreads();

        int nk = kc + STAGES - 1;
        if (nk < nCh) {
            uint32_t sb = sbase + (nk % STAGES) * STG_B;
            long kB = (long)nk * 32;
#pragma unroll
            for (int p = 0; p < 4; p++)
                cpa16(sb + dstA[p], srcA[p] + kB, szA[p]);
#pragma unroll
            for (int j = 0; j < 4; j++)
                cpa16(sb + dstB + j * 128, srcB + kB * N + j * 32, 16);
        }
        cp_commit();

        uint32_t sb = sbase + (kc % STAGES) * STG_B;
#pragma unroll
        for (int ks = 0; ks < 4; ks++) {
            uint32_t ar[4][4], br[4][2];
#pragma unroll
            for (int mt = 0; mt < 4; mt++)
                ldsm4(ar[mt], sb + aRowOff + mt * 2304 + ks * 32);
#pragma unroll
            for (int mt = 0; mt < 4; mt++)
#pragma unroll
                for (int q = 0; q < 4; q++) ar[mt][q] = u2tf(ar[mt][q]);
            uint32_t ba = sb + bColOff + ks * (8 * 528);
#pragma unroll
            for (int nt = 0; nt < 4; nt++) {
                br[nt][0] = f2tf(ldsf(ba + nt * 32));
                br[nt][1] = f2tf(ldsf(ba + nt * 32 + 4 * 528));
            }
#pragma unroll
            for (int mt = 0; mt < 4; mt++)
#pragma unroll
                for (int nt = 0; nt < 4; nt++)
                    mma16n8k8(acc[mt][nt], ar[mt], br[nt]);
        }
    }

    /* epilogue */
#pragma unroll
    for (int mt = 0; mt < 4; mt++) {
        int rl0 = mBase + warp_m * 64 + mt * 16 + g;
#pragma unroll
        for (int half = 0; half < 2; half++) {
            int rl = rl0 + half * 8;
            if (rl >= rows) continue;
            long cRow = row0 + rl;
            float* Crow = C + cRow * (long)ldc;
            const float* Rrow = resid ? (resid + cRow * (long)ldc) : (const float*)0;
#pragma unroll
            for (int nt = 0; nt < 4; nt++) {
                int c = nBase + warp_n * 32 + nt * 8 + 2 * t;
                float v0 = acc[mt][nt][half * 2 + 0];
                float v1 = acc[mt][nt][half * 2 + 1];
                if (bi)   { v0 += bi[c];   v1 += bi[c + 1]; }
                if (Rrow) { v0 += Rrow[c]; v1 += Rrow[c + 1]; }
                *(float2*)(Crow + c) = make_float2(v0, v1);
            }
        }
    }
}

/* ------------------------- flash-style attention -------------------------- */
__global__ void __launch_bounds__(128)
k_attn() {
    int qt = blockIdx.x;
    int h  = blockIdx.y;
    int b  = blockIdx.z;
    int g  = h / HPG;
    int i  = qt * 128 + threadIdx.x;

    __shared__ float Ks[64][DK];
    __shared__ float Vs[64][DK];

    float q[DK];
    const float* qp = g_q + ((size_t)(b * SEQ + i)) * DM + h * DK;
#pragma unroll
    for (int d = 0; d < DK; d++) q[d] = qp[d] * 0.125f;

    float o[DK];
#pragma unroll
    for (int d = 0; d < DK; d++) o[d] = 0.f;
    float m = -1e30f, l = 0.f;

    int ktmax = (qt * 128 + 127) / 64;
    for (int kt = 0; kt <= ktmax; kt++) {
        int j0 = kt * 64;
        __syncthreads();
        for (int tt = threadIdx.x; tt < 64 * DK; tt += 128) {
            int jj = tt / DK, d = tt % DK;
            size_t src = ((size_t)(b * SEQ + j0 + jj)) * (NG * DK) + g * DK + d;
            Ks[jj][d] = g_k[src];
            Vs[jj][d] = g_v[src];
        }
        __syncthreads();

        for (int c0 = 0; c0 < 64; c0 += 32) {
            float s[32];
            for (int jj = 0; jj < 32; jj++) {
                float acc = 0.f;
#pragma unroll
                for (int d = 0; d < DK; d++) acc += q[d] * Ks[c0 + jj][d];
                s[jj] = (j0 + c0 + jj <= i) ? acc : -1e30f;
            }
            float mn = m;
            for (int jj = 0; jj < 32; jj++) mn = fmaxf(mn, s[jj]);
            float scale = __expf(m - mn);
            m = mn;
            l *= scale;
#pragma unroll
            for (int d = 0; d < DK; d++) o[d] *= scale;
            for (int jj = 0; jj < 32; jj++) {
                float p = (j0 + c0 + jj <= i) ? __expf(s[jj] - mn) : 0.f;
                l += p;
#pragma unroll
                for (int d = 0; d < DK; d++) o[d] += p * Vs[c0 + jj][d];
            }
        }
    }

    float invl = 1.f / l;
    float* op = g_attn + ((size_t)(b * SEQ + i)) * DM + h * DK;
#pragma unroll
    for (int d = 0; d < DK; d++) op[d] = o[d] * invl;
}

/* ------------------------------- MoE routing ------------------------------ */

__global__ void k_router(const float* __restrict__ rw,
                         const float* __restrict__ rb) {
    int t    = blockIdx.x * 8 + (threadIdx.x >> 5);
    int lane = threadIdx.x & 31;
    float part[NE];
#pragma unroll
    for (int e = 0; e < NE; e++) part[e] = 0.f;
    const float* hp = g_hn + (size_t)t * DM;
    for (int d = lane; d < DM; d += 32) {
        float hv = hp[d];
        const float* rp = rw + (size_t)d * NE;
#pragma unroll
        for (int e = 0; e < NE; e++) part[e] += hv * rp[e];
    }
#pragma unroll
    for (int e = 0; e < NE; e++)
        for (int off = 16; off > 0; off >>= 1)
            part[e] += __shfl_xor_sync(0xffffffffu, part[e], off);
    if (lane == 0) {
        float lg[NE];
#pragma unroll
        for (int e = 0; e < NE; e++) lg[e] = part[e] + rb[e];
        int i0 = 0;
        for (int e = 1; e < NE; e++) if (lg[e] > lg[i0]) i0 = e;
        int i1 = (i0 == 0) ? 1 : 0;
        for (int e = 0; e < NE; e++)
            if (e != i0 && lg[e] > lg[i1]) i1 = e;
        float e1 = __expf(lg[i1] - lg[i0]);
        float inv = 1.f / (1.f + e1);
        g_tidx[t * 2 + 0] = i0; g_tidx[t * 2 + 1] = i1;
        g_twgt[t * 2 + 0] = inv; g_twgt[t * 2 + 1] = e1 * inv;
        atomicAdd(&g_cnt[i0], 1);
        atomicAdd(&g_cnt[i1], 1);
    }
}

__global__ void k_scan() {
    if (threadIdx.x == 0) {
        int acc = 0;
        for (int e = 0; e < NE; e++) {
            g_off[e] = acc; acc += g_cnt[e]; g_cur[e] = 0;
        }
        g_off[NE] = acc;
    }
}

__global__ void k_scatter() {
    int t = blockIdx.x * 256 + threadIdx.x;
    if (t >= NTOK) return;
#pragma unroll
    for (int k = 0; k < 2; k++) {
        int e = g_tidx[t * 2 + k];
        int p = atomicAdd(&g_cur[e], 1);
        int row = g_off[e] + p;
        g_tok[row] = t;
        g_trow[t * 2 + k] = row;
    }
}

__global__ void k_silu() {
    size_t i = ((size_t)blockIdx.x * 256 + threadIdx.x) * 4;
    float4 a = *(float4*)&g_h1[i];
    float4 b = *(float4*)&g_h2[i];
    a.x = b.x * a.x / (1.f + __expf(-a.x));
    a.y = b.y * a.y / (1.f + __expf(-a.y));
    a.z = b.z * a.z / (1.f + __expf(-a.z));
    a.w = b.w * a.w / (1.f + __expf(-a.w));
    *(float4*)&g_h1[i] = a;
}

__global__ void k_combine(float* __restrict__ out) {
    int t = blockIdx.x;
    int   r0 = g_trow[t * 2],     r1 = g_trow[t * 2 + 1];
    float w0 = g_twgt[t * 2],     w1 = g_twgt[t * 2 + 1];
    const float* e0 = g_eo + (size_t)r0 * DM;
    const float* e1 = g_eo + (size_t)r1 * DM;
    float* op = out + (size_t)t * DM;
    for (int d = threadIdx.x; d < DM; d += 256)
        op[d] += w0 * e0[d] + w1 * e1[d];
}

/* --------------------------------- driver --------------------------------- */

extern "C" void kernel_launch(void* const* d_in, const int* in_sizes, int n_in,
                              void* d_out, int out_size) {
    const float* x   = (const float*)d_in[0];
    const float* n1w = (const float*)d_in[1];
    const float* Wq  = (const float*)d_in[2];
    const float* Wk  = (const float*)d_in[3];
    const float* Wv  = (const float*)d_in[4];
    const float* Wo  = (const float*)d_in[5];
    const float* n2w = (const float*)d_in[6];
    const float* rw  = (const float*)d_in[7];
    const float* rb  = (const float*)d_in[8];
    const float* W1  = (const float*)d_in[9];
    const float* b1  = (const float*)d_in[10];
    const float* W2  = (const float*)d_in[11];
    const float* b2  = (const float*)d_in[12];
    const float* W3  = (const float*)d_in[13];
    const float* b3  = (const float*)d_in[14];
    float* out = (float*)d_out;

    cudaFuncSetAttribute(k_tgemm, cudaFuncAttributeMaxDynamicSharedMemorySize,
                         TG_SMEM);

    void *p_xr, *p_q, *p_k, *p_v, *p_attn, *p_hn, *p_h1, *p_h2, *p_eo, *p_off, *p_tok;
    cudaGetSymbolAddress(&p_xr,  g_xr);
    cudaGetSymbolAddress(&p_q,   g_q);
    cudaGetSymbolAddress(&p_k,   g_k);
    cudaGetSymbolAddress(&p_v,   g_v);
    cudaGetSymbolAddress(&p_attn,g_attn);
    cudaGetSymbolAddress(&p_hn,  g_hn);
    cudaGetSymbolAddress(&p_h1,  g_h1);
    cudaGetSymbolAddress(&p_h2,  g_h2);
    cudaGetSymbolAddress(&p_eo,  g_eo);
    cudaGetSymbolAddress(&p_off, g_off);
    cudaGetSymbolAddress(&p_tok, g_tok);
    float* xr   = (float*)p_xr;
    float* qb   = (float*)p_q;
    float* kb   = (float*)p_k;
    float* vb   = (float*)p_v;
    float* attn = (float*)p_attn;
    float* hn   = (float*)p_hn;
    float* h1b  = (float*)p_h1;
    float* h2b  = (float*)p_h2;
    float* eob  = (float*)p_eo;
    int*   offp = (int*)p_off;
    int*   tokp = (int*)p_tok;

    k_zero<<<1, 32>>>();
    k_norm_rope<<<NTOK, 256>>>(x, n1w);

    /* QKV projections */
    k_tgemm<<<dim3(DM/128, NTOK/128, 1), 256, TG_SMEM>>>(
        xr, DM, Wq, 0, 0, 0, 0, qb, DM, NTOK, DM, DM, 0, 0);
    k_tgemm<<<dim3((NG*DK)/128, NTOK/128, 1), 256, TG_SMEM>>>(
        xr, DM, Wk, 0, 0, 0, 0, kb, NG*DK, NTOK, NG*DK, DM, 0, 0);
    k_tgemm<<<dim3((NG*DK)/128, NTOK/128, 1), 256, TG_SMEM>>>(
        xr, DM, Wv, 0, 0, 0, 0, vb, NG*DK, NTOK, NG*DK, DM, 0, 0);

    k_attn<<<dim3(SEQ/128, NH, BATCH), 128>>>();

    /* out = x + attn @ Wo */
    k_tgemm<<<dim3(DM/128, NTOK/128, 1), 256, TG_SMEM>>>(
        attn, DM, Wo, 0, 0, 0, x, out, DM, NTOK, DM, DM, 0, 0);

    k_rmsnorm<<<NTOK, 256>>>(out, n2w);

    k_router<<<NTOK/8, 256>>>(rw, rb);
    k_scan<<<1, 32>>>();
    k_scatter<<<NTOK/256, 256>>>();

    /* expert FFN */
    k_tgemm<<<dim3(DFF/128, NTOK/128, NE), 256, TG_SMEM>>>(
        hn, DM, W1, (long)DM*DFF, b1, DFF, 0,
        h1b, DFF, 0, DFF, DM, offp, tokp);
    k_tgemm<<<dim3(DFF/128, NTOK/128, NE), 256, TG_SMEM>>>(
        hn, DM, W2, (long)DM*DFF, b2, DFF, 0,
        h2b, DFF, 0, DFF, DM, offp, tokp);
    k_silu<<<(NASSIGN*(DFF/4))/256, 256>>>();
    k_tgemm<<<dim3(DM/128, NTOK/128, NE), 256, TG_SMEM>>>(
        h1b, DFF, W3, (long)DFF*DM, b3, DM, 0,
        eob, DM, 0, DM, DFF, offp, 0);

    k_combine<<<NTOK, 256>>>(out);
}

// round 8
// speedup vs baseline: 3.0174x; 1.0675x over previous
#include <cuda_runtime.h>
#include <stdint.h>
#include <math.h>

#define BATCH 2
#define SEQ   1024
#define DM    1024
#define NH    16
#define DK    64
#define NG    4
#define HPG   4
#define DFF   4096
#define NE    8
#define NTOK  (BATCH*SEQ)      /* 2048 */
#define NASSIGN (NTOK*2)       /* 4096 */

/* ------------------------- scratch (device globals) ------------------------ */
__device__ float g_xr[NTOK*DM];          /* tf32-rounded */
__device__ float g_q [NTOK*DM];
__device__ float g_k [NTOK*NG*DK];
__device__ float g_v [NTOK*NG*DK];
__device__ float g_attn[NTOK*DM];        /* tf32-rounded */
__device__ float g_hn[NTOK*DM];          /* exact fp32 (router) */
__device__ float g_hnr[NTOK*DM];         /* tf32-rounded (GEMM A) */
__device__ float g_h1[(size_t)NASSIGN*DFF];
__device__ float g_h2[(size_t)NASSIGN*DFF];
__device__ float g_eo[NASSIGN*DM];
__device__ int   g_cnt[NE];
__device__ int   g_off[NE+1];
__device__ int   g_cur[NE];
__device__ int   g_tok[NASSIGN];
__device__ int   g_tidx[NTOK*2];
__device__ float g_twgt[NTOK*2];
__device__ int   g_trow[NTOK*2];

/* ------------------------------ helpers ----------------------------------- */

__device__ __forceinline__ uint32_t f2tf(float x){
    uint32_t r; asm("cvt.rna.tf32.f32 %0, %1;" : "=r"(r) : "f"(x)); return r;
}
__device__ __forceinline__ float f2tff(float x){
    return __uint_as_float(f2tf(x));
}
__device__ __forceinline__ void mma16n8k8(float* c, const uint32_t* a,
                                          const uint32_t* b){
    asm("mma.sync.aligned.m16n8k8.row.col.f32.tf32.tf32.f32 "
        "{%0,%1,%2,%3}, {%4,%5,%6,%7}, {%8,%9}, {%0,%1,%2,%3};"
        : "+f"(c[0]), "+f"(c[1]), "+f"(c[2]), "+f"(c[3])
        : "r"(a[0]), "r"(a[1]), "r"(a[2]), "r"(a[3]),
          "r"(b[0]), "r"(b[1]));
}
__device__ __forceinline__ void ldsm4(uint32_t* r, uint32_t addr){
    asm("ldmatrix.sync.aligned.m8n8.x4.shared.b16 {%0,%1,%2,%3}, [%4];"
        : "=r"(r[0]), "=r"(r[1]), "=r"(r[2]), "=r"(r[3]) : "r"(addr));
}
__device__ __forceinline__ float ldsf(uint32_t a){
    float v; asm("ld.shared.f32 %0, [%1];" : "=f"(v) : "r"(a)); return v;
}
__device__ __forceinline__ void cpa16(uint32_t dst, const void* src, int sz){
    asm volatile("cp.async.cg.shared.global [%0], [%1], 16, %2;"
                 :: "r"(dst), "l"(src), "r"(sz));
}
__device__ __forceinline__ void cp_commit(){
    asm volatile("cp.async.commit_group;");
}
__device__ __forceinline__ void cp_wait1(){
    asm volatile("cp.async.wait_group 1;");
}

/* ------------------------------ small kernels ------------------------------ */

__global__ void k_zero() {
    if (threadIdx.x < NE) g_cnt[threadIdx.x] = 0;
}

__global__ void k_norm_rope(const float* __restrict__ x,
                            const float* __restrict__ w) {
    int row = blockIdx.x;
    int s   = row % SEQ;
    __shared__ float xs[DM];
    __shared__ float red[256];
    const float* xp = x + (size_t)row * DM;
    float ss = 0.f;
    for (int d = threadIdx.x; d < DM; d += 256) {
        float v = xp[d]; xs[d] = v; ss += v * v;
    }
    red[threadIdx.x] = ss; __syncthreads();
    for (int st = 128; st > 0; st >>= 1) {
        if (threadIdx.x < st) red[threadIdx.x] += red[threadIdx.x + st];
        __syncthreads();
    }
    float inv = rsqrtf(red[0] / (float)DM + 1e-6f);
    float* op = g_xr + (size_t)row * DM;
    for (int k = threadIdx.x; k < DM / 2; k += 256) {
        float theta = powf(10000.f, -(float)k / (float)(DM / 2));
        float ang = (float)s * theta;
        float sn, cs; sincosf(ang, &sn, &cs);
        float xe = xs[2 * k]     * inv * w[2 * k];
        float xo = xs[2 * k + 1] * inv * w[2 * k + 1];
        op[k]          = f2tff(xe * cs - xo * sn);
        op[DM / 2 + k] = f2tff(xe * sn + xo * cs);
    }
}

/* writes exact fp32 to g_hn (router) and tf32-rounded to g_hnr (GEMM A) */
__global__ void k_rmsnorm(const float* __restrict__ src,
                          const float* __restrict__ w) {
    int row = blockIdx.x;
    __shared__ float red[256];
    const float* xp = src + (size_t)row * DM;
    float ss = 0.f;
    for (int d = threadIdx.x; d < DM; d += 256) { float v = xp[d]; ss += v * v; }
    red[threadIdx.x] = ss; __syncthreads();
    for (int st = 128; st > 0; st >>= 1) {
        if (threadIdx.x < st) red[threadIdx.x] += red[threadIdx.x + st];
        __syncthreads();
    }
    float inv = rsqrtf(red[0] / (float)DM + 1e-6f);
    float* op  = g_hn  + (size_t)row * DM;
    float* opr = g_hnr + (size_t)row * DM;
    for (int d = threadIdx.x; d < DM; d += 256) {
        float v = xp[d] * inv * w[d];
        op[d]  = v;
        opr[d] = f2tff(v);
    }
}

/* ------------- warp-MMA tf32 GEMM body, cp.async 3-stage pipeline ----------
   A must be pre-rounded to tf32 (low 13 mantissa bits zero); B cvt in-loop.
   BM=128 BN=128 BK=32, 256 thr, 8 warps (2m x 4n), warp tile 64x32.
   A smem [m][k] 144B rows -> ldmatrix x4 raw; B smem [k][n] 528B rows.     */
#define STAGES   3
#define A_STG    18432
#define B_STG    16896
#define STG_B    (A_STG + B_STG)       /* 35328 */
#define TG_SMEM  (STAGES * STG_B)      /* 105984 */

__device__ __forceinline__ void gemm_body(
        const float* __restrict__ A, int lda,
        const float* __restrict__ Bp, int Bn,
        const float* __restrict__ bi,
        const float* __restrict__ resid,
        float* __restrict__ C, int ldc,
        int rows, int row0, int mBase, int nBase, int K,
        const int* __restrict__ rowmap) {
    extern __shared__ __align__(128) char smem[];

    uint32_t sbase = (uint32_t)__cvta_generic_to_shared(smem);
    int tid = threadIdx.x, lane = tid & 31, wid = tid >> 5;
    int g = lane >> 2, t = lane & 3;
    int warp_m = wid & 1, warp_n = wid >> 1;

    const float* srcA[4]; int szA[4]; uint32_t dstA[4];
    int ac = tid & 7;
#pragma unroll
    for (int p = 0; p < 4; p++) {
        int m  = p * 32 + (tid >> 3);
        int rl = mBase + m;
        bool v = rl < rows;
        long ai = 0;
        if (v) ai = rowmap ? (long)rowmap[row0 + rl] : (long)(row0 + rl);
        srcA[p] = A + ai * (long)lda + ac * 4;
        szA[p]  = v ? 16 : 0;
        dstA[p] = (uint32_t)(m * 144 + ac * 16);
    }
    int bkr = tid >> 3;
    const float* srcB = Bp + (long)bkr * Bn + nBase + (tid & 7) * 4;
    uint32_t dstB = A_STG + (uint32_t)(bkr * 528 + (tid & 7) * 16);

    uint32_t aRowOff = (uint32_t)((warp_m * 64 + (lane & 15)) * 144
                                  + ((lane >> 4) << 4));
    uint32_t bColOff = (uint32_t)(A_STG + (warp_n * 32 + g) * 4 + t * 528);

    float acc[4][4][4];
#pragma unroll
    for (int i = 0; i < 4; i++)
#pragma unroll
        for (int j = 0; j < 4; j++)
#pragma unroll
            for (int q = 0; q < 4; q++) acc[i][j][q] = 0.f;

    int nCh = K >> 5;

#pragma unroll
    for (int s = 0; s < STAGES - 1; s++) {
        if (s < nCh) {
            uint32_t sb = sbase + s * STG_B;
            long kB = (long)s * 32;
#pragma unroll
            for (int p = 0; p < 4; p++)
                cpa16(sb + dstA[p], srcA[p] + kB, szA[p]);
#pragma unroll
            for (int j = 0; j < 4; j++)
                cpa16(sb + dstB + j * 128, srcB + kB * Bn + j * 32, 16);
        }
        cp_commit();
    }

    for (int kc = 0; kc < nCh; kc++) {
        cp_wait1();
        __syncthreads();

        int nk = kc + STAGES - 1;
        if (nk < nCh) {
            uint32_t sb = sbase + (nk % STAGES) * STG_B;
            long kB = (long)nk * 32;
#pragma unroll
            for (int p = 0; p < 4; p++)
                cpa16(sb + dstA[p], srcA[p] + kB, szA[p]);
#pragma unroll
            for (int j = 0; j < 4; j++)
                cpa16(sb + dstB + j * 128, srcB + kB * Bn + j * 32, 16);
        }
        cp_commit();

        uint32_t sb = sbase + (kc % STAGES) * STG_B;
#pragma unroll
        for (int ks = 0; ks < 4; ks++) {
            uint32_t ar[4][4], br[4][2];
#pragma unroll
            for (int mt = 0; mt < 4; mt++)
                ldsm4(ar[mt], sb + aRowOff + mt * 2304 + ks * 32);
            uint32_t ba = sb + bColOff + ks * (8 * 528);
#pragma unroll
            for (int nt = 0; nt < 4; nt++) {
                br[nt][0] = f2tf(ldsf(ba + nt * 32));
                br[nt][1] = f2tf(ldsf(ba + nt * 32 + 4 * 528));
            }
#pragma unroll
            for (int mt = 0; mt < 4; mt++)
#pragma unroll
                for (int nt = 0; nt < 4; nt++)
                    mma16n8k8(acc[mt][nt], ar[mt], br[nt]);
        }
    }

#pragma unroll
    for (int mt = 0; mt < 4; mt++) {
        int rl0 = mBase + warp_m * 64 + mt * 16 + g;
#pragma unroll
        for (int half = 0; half < 2; half++) {
            int rl = rl0 + half * 8;
            if (rl >= rows) continue;
            long cRow = row0 + rl;
            float* Crow = C + cRow * (long)ldc;
            const float* Rrow = resid ? (resid + cRow * (long)ldc) : (const float*)0;
#pragma unroll
            for (int nt = 0; nt < 4; nt++) {
                int c = nBase + warp_n * 32 + nt * 8 + 2 * t;
                float v0 = acc[mt][nt][half * 2 + 0];
                float v1 = acc[mt][nt][half * 2 + 1];
                if (bi)   { v0 += bi[c];   v1 += bi[c + 1]; }
                if (Rrow) { v0 += Rrow[c]; v1 += Rrow[c + 1]; }
                *(float2*)(Crow + c) = make_float2(v0, v1);
            }
        }
    }
}

__global__ void __launch_bounds__(256)
k_tgemm(const float* __restrict__ A, int lda,
        const float* __restrict__ Bmat, long bstride,
        const float* __restrict__ bias, long biasStride,
        const float* __restrict__ resid,
        float* __restrict__ C, int ldc,
        int M, int N, int K,
        const int* __restrict__ segoff,
        const int* __restrict__ rowmap) {
    int e = blockIdx.z;
    int row0 = 0, rows = M;
    if (segoff) { row0 = segoff[e]; rows = segoff[e + 1] - row0; }
    int mBase = blockIdx.y * 128;
    if (mBase >= rows) return;
    gemm_body(A, lda,
              Bmat + (long)e * bstride, N,
              bias ? (bias + (long)e * biasStride) : (const float*)0,
              resid, C, ldc,
              rows, row0, mBase, blockIdx.x * 128, K, rowmap);
}

/* fused Q/K/V projection: grid (12, 16); x<8 -> Q, 8..9 -> K, 10..11 -> V */
__global__ void __launch_bounds__(256)
k_qkv(const float* __restrict__ Wq, const float* __restrict__ Wk,
      const float* __restrict__ Wv) {
    int x = blockIdx.x;
    const float* B; float* C; int Bn, col0;
    if (x < 8)       { B = Wq; C = g_q; Bn = DM;      col0 = x * 128; }
    else if (x < 10) { B = Wk; C = g_k; Bn = NG * DK; col0 = (x - 8) * 128; }
    else             { B = Wv; C = g_v; Bn = NG * DK; col0 = (x - 10) * 128; }
    gemm_body(g_xr, DM, B, Bn, 0, 0, C, Bn,
              NTOK, 0, blockIdx.y * 128, col0, DM, 0);
}

/* ------------------------- flash-style attention -------------------------- */
__global__ void __launch_bounds__(128)
k_attn() {
    int qt = blockIdx.x;
    int h  = blockIdx.y;
    int b  = blockIdx.z;
    int g  = h / HPG;
    int i  = qt * 128 + threadIdx.x;

    __shared__ float Ks[64][DK];
    __shared__ float Vs[64][DK];

    float q[DK];
    const float* qp = g_q + ((size_t)(b * SEQ + i)) * DM + h * DK;
#pragma unroll
    for (int d = 0; d < DK; d++) q[d] = qp[d] * 0.125f;

    float o[DK];
#pragma unroll
    for (int d = 0; d < DK; d++) o[d] = 0.f;
    float m = -1e30f, l = 0.f;

    int ktmax = (qt * 128 + 127) / 64;
    for (int kt = 0; kt <= ktmax; kt++) {
        int j0 = kt * 64;
        __syncthreads();
        for (int tt = threadIdx.x; tt < 64 * DK; tt += 128) {
            int jj = tt / DK, d = tt % DK;
            size_t src = ((size_t)(b * SEQ + j0 + jj)) * (NG * DK) + g * DK + d;
            Ks[jj][d] = g_k[src];
            Vs[jj][d] = g_v[src];
        }
        __syncthreads();

        for (int c0 = 0; c0 < 64; c0 += 32) {
            float s[32];
            for (int jj = 0; jj < 32; jj++) {
                float acc = 0.f;
#pragma unroll
                for (int d = 0; d < DK; d++) acc += q[d] * Ks[c0 + jj][d];
                s[jj] = (j0 + c0 + jj <= i) ? acc : -1e30f;
            }
            float mn = m;
            for (int jj = 0; jj < 32; jj++) mn = fmaxf(mn, s[jj]);
            float scale = __expf(m - mn);
            m = mn;
            l *= scale;
#pragma unroll
            for (int d = 0; d < DK; d++) o[d] *= scale;
            for (int jj = 0; jj < 32; jj++) {
                float p = (j0 + c0 + jj <= i) ? __expf(s[jj] - mn) : 0.f;
                l += p;
#pragma unroll
                for (int d = 0; d < DK; d++) o[d] += p * Vs[c0 + jj][d];
            }
        }
    }

    float invl = 1.f / l;
    float* op = g_attn + ((size_t)(b * SEQ + i)) * DM + h * DK;
#pragma unroll
    for (int d = 0; d < DK; d++) op[d] = f2tff(o[d] * invl);
}

/* ------------------------------- MoE routing ------------------------------ */

__global__ void k_router(const float* __restrict__ rw,
                         const float* __restrict__ rb) {
    int t    = blockIdx.x * 8 + (threadIdx.x >> 5);
    int lane = threadIdx.x & 31;
    float part[NE];
#pragma unroll
    for (int e = 0; e < NE; e++) part[e] = 0.f;
    const float* hp = g_hn + (size_t)t * DM;
    for (int d = lane; d < DM; d += 32) {
        float hv = hp[d];
        const float* rp = rw + (size_t)d * NE;
#pragma unroll
        for (int e = 0; e < NE; e++) part[e] += hv * rp[e];
    }
#pragma unroll
    for (int e = 0; e < NE; e++)
        for (int off = 16; off > 0; off >>= 1)
            part[e] += __shfl_xor_sync(0xffffffffu, part[e], off);
    if (lane == 0) {
        float lg[NE];
#pragma unroll
        for (int e = 0; e < NE; e++) lg[e] = part[e] + rb[e];
        int i0 = 0;
        for (int e = 1; e < NE; e++) if (lg[e] > lg[i0]) i0 = e;
        int i1 = (i0 == 0) ? 1 : 0;
        for (int e = 0; e < NE; e++)
            if (e != i0 && lg[e] > lg[i1]) i1 = e;
        float e1 = __expf(lg[i1] - lg[i0]);
        float inv = 1.f / (1.f + e1);
        g_tidx[t * 2 + 0] = i0; g_tidx[t * 2 + 1] = i1;
        g_twgt[t * 2 + 0] = inv; g_twgt[t * 2 + 1] = e1 * inv;
        atomicAdd(&g_cnt[i0], 1);
        atomicAdd(&g_cnt[i1], 1);
    }
}

__global__ void k_scan() {
    if (threadIdx.x == 0) {
        int acc = 0;
        for (int e = 0; e < NE; e++) {
            g_off[e] = acc; acc += g_cnt[e]; g_cur[e] = 0;
        }
        g_off[NE] = acc;
    }
}

__global__ void k_scatter() {
    int t = blockIdx.x * 256 + threadIdx.x;
    if (t >= NTOK) return;
#pragma unroll
    for (int k = 0; k < 2; k++) {
        int e = g_tidx[t * 2 + k];
        int p = atomicAdd(&g_cur[e], 1);
        int row = g_off[e] + p;
        g_tok[row] = t;
        g_trow[t * 2 + k] = row;
    }
}

__global__ void k_silu() {
    size_t i = ((size_t)blockIdx.x * 256 + threadIdx.x) * 4;
    float4 a = *(float4*)&g_h1[i];
    float4 b = *(float4*)&g_h2[i];
    a.x = f2tff(b.x * a.x / (1.f + __expf(-a.x)));
    a.y = f2tff(b.y * a.y / (1.f + __expf(-a.y)));
    a.z = f2tff(b.z * a.z / (1.f + __expf(-a.z)));
    a.w = f2tff(b.w * a.w / (1.f + __expf(-a.w)));
    *(float4*)&g_h1[i] = a;
}

__global__ void k_combine(float* __restrict__ out) {
    int t = blockIdx.x;
    int   r0 = g_trow[t * 2],     r1 = g_trow[t * 2 + 1];
    float w0 = g_twgt[t * 2],     w1 = g_twgt[t * 2 + 1];
    const float* e0 = g_eo + (size_t)r0 * DM;
    const float* e1 = g_eo + (size_t)r1 * DM;
    float* op = out + (size_t)t * DM;
    for (int d = threadIdx.x; d < DM; d += 256)
        op[d] += w0 * e0[d] + w1 * e1[d];
}

/* --------------------------------- driver --------------------------------- */

extern "C" void kernel_launch(void* const* d_in, const int* in_sizes, int n_in,
                              void* d_out, int out_size) {
    const float* x   = (const float*)d_in[0];
    const float* n1w = (const float*)d_in[1];
    const float* Wq  = (const float*)d_in[2];
    const float* Wk  = (const float*)d_in[3];
    const float* Wv  = (const float*)d_in[4];
    const float* Wo  = (const float*)d_in[5];
    const float* n2w = (const float*)d_in[6];
    const float* rw  = (const float*)d_in[7];
    const float* rb  = (const float*)d_in[8];
    const float* W1  = (const float*)d_in[9];
    const float* b1  = (const float*)d_in[10];
    const float* W2  = (const float*)d_in[11];
    const float* b2  = (const float*)d_in[12];
    const float* W3  = (const float*)d_in[13];
    const float* b3  = (const float*)d_in[14];
    float* out = (float*)d_out;

    cudaFuncSetAttribute(k_tgemm, cudaFuncAttributeMaxDynamicSharedMemorySize,
                         TG_SMEM);
    cudaFuncSetAttribute(k_qkv, cudaFuncAttributeMaxDynamicSharedMemorySize,
                         TG_SMEM);

    void *p_attn, *p_hnr, *p_h1, *p_h2, *p_eo, *p_off, *p_tok;
    cudaGetSymbolAddress(&p_attn, g_attn);
    cudaGetSymbolAddress(&p_hnr,  g_hnr);
    cudaGetSymbolAddress(&p_h1,   g_h1);
    cudaGetSymbolAddress(&p_h2,   g_h2);
    cudaGetSymbolAddress(&p_eo,   g_eo);
    cudaGetSymbolAddress(&p_off,  g_off);
    cudaGetSymbolAddress(&p_tok,  g_tok);
    float* attn = (float*)p_attn;
    float* hnr  = (float*)p_hnr;
    float* h1b  = (float*)p_h1;
    float* h2b  = (float*)p_h2;
    float* eob  = (float*)p_eo;
    int*   offp = (int*)p_off;
    int*   tokp = (int*)p_tok;

    k_zero<<<1, 32>>>();
    k_norm_rope<<<NTOK, 256>>>(x, n1w);

    /* fused Q/K/V projections */
    k_qkv<<<dim3(12, NTOK/128, 1), 256, TG_SMEM>>>(Wq, Wk, Wv);

    k_attn<<<dim3(SEQ/128, NH, BATCH), 128>>>();

    /* out = x + attn @ Wo */
    k_tgemm<<<dim3(DM/128, NTOK/128, 1), 256, TG_SMEM>>>(
        attn, DM, Wo, 0, 0, 0, x, out, DM, NTOK, DM, DM, 0, 0);

    k_rmsnorm<<<NTOK, 256>>>(out, n2w);

    k_router<<<NTOK/8, 256>>>(rw, rb);
    k_scan<<<1, 32>>>();
    k_scatter<<<NTOK/256, 256>>>();

    /* expert FFN */
    k_tgemm<<<dim3(DFF/128, NTOK/128, NE), 256, TG_SMEM>>>(
        hnr, DM, W1, (long)DM*DFF, b1, DFF, 0,
        h1b, DFF, 0, DFF, DM, offp, tokp);
    k_tgemm<<<dim3(DFF/128, NTOK/128, NE), 256, TG_SMEM>>>(
        hnr, DM, W2, (long)DM*DFF, b2, DFF, 0,
        h2b, DFF, 0, DFF, DM, offp, tokp);
    k_silu<<<(NASSIGN*(DFF/4))/256, 256>>>();
    k_tgemm<<<dim3(DM/128, NTOK/128, NE), 256, TG_SMEM>>>(
        h1b, DFF, W3, (long)DFF*DM, b3, DM, 0,
        eob, DM, 0, DM, DFF, offp, 0);

    k_combine<<<NTOK, 256>>>(out);
}

// round 9
// speedup vs baseline: 3.1897x; 1.0571x over previous
#include <cuda_runtime.h>
#include <stdint.h>
#include <math.h>

#define BATCH 2
#define SEQ   1024
#define DM    1024
#define NH    16
#define DK    64
#define NG    4
#define HPG   4
#define DFF   4096
#define NE    8
#define NTOK  (BATCH*SEQ)      /* 2048 */
#define NASSIGN (NTOK*2)       /* 4096 */
#define NROWS (BATCH*NH*SEQ)   /* 32768 attention rows */

/* ------------------------- scratch (device globals) ------------------------ */
__device__ float g_xr[NTOK*DM];          /* tf32-rounded */
__device__ float g_q [NTOK*DM];
__device__ float g_k [NTOK*NG*DK];
__device__ float g_v [NTOK*NG*DK];
__device__ float g_attn[NTOK*DM];        /* tf32-rounded */
__device__ float g_hn[NTOK*DM];          /* exact fp32 (router) */
__device__ float g_hnr[NTOK*DM];         /* tf32-rounded (GEMM A) */
__device__ float g_h1[(size_t)NASSIGN*DFF];  /* MoE h1; aliased as attn partial o */
__device__ float g_h2[(size_t)NASSIGN*DFF];  /* MoE h2; aliased as attn partial (m,l) */
__device__ float g_eo[NASSIGN*DM];
__device__ int   g_cnt[NE];
__device__ int   g_off[NE+1];
__device__ int   g_cur[NE];
__device__ int   g_tok[NASSIGN];
__device__ int   g_tidx[NTOK*2];
__device__ float g_twgt[NTOK*2];
__device__ int   g_trow[NTOK*2];

/* ------------------------------ helpers ----------------------------------- */

__device__ __forceinline__ uint32_t f2tf(float x){
    uint32_t r; asm("cvt.rna.tf32.f32 %0, %1;" : "=r"(r) : "f"(x)); return r;
}
__device__ __forceinline__ float f2tff(float x){
    return __uint_as_float(f2tf(x));
}
__device__ __forceinline__ void mma16n8k8(float* c, const uint32_t* a,
                                          const uint32_t* b){
    asm("mma.sync.aligned.m16n8k8.row.col.f32.tf32.tf32.f32 "
        "{%0,%1,%2,%3}, {%4,%5,%6,%7}, {%8,%9}, {%0,%1,%2,%3};"
        : "+f"(c[0]), "+f"(c[1]), "+f"(c[2]), "+f"(c[3])
        : "r"(a[0]), "r"(a[1]), "r"(a[2]), "r"(a[3]),
          "r"(b[0]), "r"(b[1]));
}
__device__ __forceinline__ void ldsm4(uint32_t* r, uint32_t addr){
    asm("ldmatrix.sync.aligned.m8n8.x4.shared.b16 {%0,%1,%2,%3}, [%4];"
        : "=r"(r[0]), "=r"(r[1]), "=r"(r[2]), "=r"(r[3]) : "r"(addr));
}
__device__ __forceinline__ float ldsf(uint32_t a){
    float v; asm("ld.shared.f32 %0, [%1];" : "=f"(v) : "r"(a)); return v;
}
__device__ __forceinline__ void cpa16(uint32_t dst, const void* src, int sz){
    asm volatile("cp.async.cg.shared.global [%0], [%1], 16, %2;"
                 :: "r"(dst), "l"(src), "r"(sz));
}
__device__ __forceinline__ void cp_commit(){
    asm volatile("cp.async.commit_group;");
}
__device__ __forceinline__ void cp_wait1(){
    asm volatile("cp.async.wait_group 1;");
}

/* ------------------------------ small kernels ------------------------------ */

__global__ void k_zero() {
    if (threadIdx.x < NE) g_cnt[threadIdx.x] = 0;
}

__global__ void k_norm_rope(const float* __restrict__ x,
                            const float* __restrict__ w) {
    int row = blockIdx.x;
    int s   = row % SEQ;
    __shared__ float xs[DM];
    __shared__ float red[256];
    const float* xp = x + (size_t)row * DM;
    float ss = 0.f;
    for (int d = threadIdx.x; d < DM; d += 256) {
        float v = xp[d]; xs[d] = v; ss += v * v;
    }
    red[threadIdx.x] = ss; __syncthreads();
    for (int st = 128; st > 0; st >>= 1) {
        if (threadIdx.x < st) red[threadIdx.x] += red[threadIdx.x + st];
        __syncthreads();
    }
    float inv = rsqrtf(red[0] / (float)DM + 1e-6f);
    float* op = g_xr + (size_t)row * DM;
    for (int k = threadIdx.x; k < DM / 2; k += 256) {
        float theta = powf(10000.f, -(float)k / (float)(DM / 2));
        float ang = (float)s * theta;
        float sn, cs; sincosf(ang, &sn, &cs);
        float xe = xs[2 * k]     * inv * w[2 * k];
        float xo = xs[2 * k + 1] * inv * w[2 * k + 1];
        op[k]          = f2tff(xe * cs - xo * sn);
        op[DM / 2 + k] = f2tff(xe * sn + xo * cs);
    }
}

/* writes exact fp32 to g_hn (router) and tf32-rounded to g_hnr (GEMM A) */
__global__ void k_rmsnorm(const float* __restrict__ src,
                          const float* __restrict__ w) {
    int row = blockIdx.x;
    __shared__ float red[256];
    const float* xp = src + (size_t)row * DM;
    float ss = 0.f;
    for (int d = threadIdx.x; d < DM; d += 256) { float v = xp[d]; ss += v * v; }
    red[threadIdx.x] = ss; __syncthreads();
    for (int st = 128; st > 0; st >>= 1) {
        if (threadIdx.x < st) red[threadIdx.x] += red[threadIdx.x + st];
        __syncthreads();
    }
    float inv = rsqrtf(red[0] / (float)DM + 1e-6f);
    float* op  = g_hn  + (size_t)row * DM;
    float* opr = g_hnr + (size_t)row * DM;
    for (int d = threadIdx.x; d < DM; d += 256) {
        float v = xp[d] * inv * w[d];
        op[d]  = v;
        opr[d] = f2tff(v);
    }
}

/* ------------- warp-MMA tf32 GEMM body, cp.async 3-stage pipeline ----------
   A must be pre-rounded to tf32 (low 13 mantissa bits zero); B cvt in-loop.
   BM=128 BN=128 BK=32, 256 thr, 8 warps (2m x 4n), warp tile 64x32.
   A smem [m][k] 144B rows -> ldmatrix x4 raw; B smem [k][n] 528B rows.     */
#define STAGES   3
#define A_STG    18432
#define B_STG    16896
#define STG_B    (A_STG + B_STG)       /* 35328 */
#define TG_SMEM  (STAGES * STG_B)      /* 105984 */

__device__ __forceinline__ void gemm_body(
        const float* __restrict__ A, int lda,
        const float* __restrict__ Bp, int Bn,
        const float* __restrict__ bi,
        const float* __restrict__ resid,
        float* __restrict__ C, int ldc,
        int rows, int row0, int mBase, int nBase, int K,
        const int* __restrict__ rowmap) {
    extern __shared__ __align__(128) char smem[];

    uint32_t sbase = (uint32_t)__cvta_generic_to_shared(smem);
    int tid = threadIdx.x, lane = tid & 31, wid = tid >> 5;
    int g = lane >> 2, t = lane & 3;
    int warp_m = wid & 1, warp_n = wid >> 1;

    const float* srcA[4]; int szA[4]; uint32_t dstA[4];
    int ac = tid & 7;
#pragma unroll
    for (int p = 0; p < 4; p++) {
        int m  = p * 32 + (tid >> 3);
        int rl = mBase + m;
        bool v = rl < rows;
        long ai = 0;
        if (v) ai = rowmap ? (long)rowmap[row0 + rl] : (long)(row0 + rl);
        srcA[p] = A + ai * (long)lda + ac * 4;
        szA[p]  = v ? 16 : 0;
        dstA[p] = (uint32_t)(m * 144 + ac * 16);
    }
    int bkr = tid >> 3;
    const float* srcB = Bp + (long)bkr * Bn + nBase + (tid & 7) * 4;
    uint32_t dstB = A_STG + (uint32_t)(bkr * 528 + (tid & 7) * 16);

    uint32_t aRowOff = (uint32_t)((warp_m * 64 + (lane & 15)) * 144
                                  + ((lane >> 4) << 4));
    uint32_t bColOff = (uint32_t)(A_STG + (warp_n * 32 + g) * 4 + t * 528);

    float acc[4][4][4];
#pragma unroll
    for (int i = 0; i < 4; i++)
#pragma unroll
        for (int j = 0; j < 4; j++)
#pragma unroll
            for (int q = 0; q < 4; q++) acc[i][j][q] = 0.f;

    int nCh = K >> 5;

#pragma unroll
    for (int s = 0; s < STAGES - 1; s++) {
        if (s < nCh) {
            uint32_t sb = sbase + s * STG_B;
            long kB = (long)s * 32;
#pragma unroll
            for (int p = 0; p < 4; p++)
                cpa16(sb + dstA[p], srcA[p] + kB, szA[p]);
#pragma unroll
            for (int j = 0; j < 4; j++)
                cpa16(sb + dstB + j * 128, srcB + kB * Bn + j * 32, 16);
        }
        cp_commit();
    }

    for (int kc = 0; kc < nCh; kc++) {
        cp_wait1();
        __syncthreads();

        int nk = kc + STAGES - 1;
        if (nk < nCh) {
            uint32_t sb = sbase + (nk % STAGES) * STG_B;
            long kB = (long)nk * 32;
#pragma unroll
            for (int p = 0; p < 4; p++)
                cpa16(sb + dstA[p], srcA[p] + kB, szA[p]);
#pragma unroll
            for (int j = 0; j < 4; j++)
                cpa16(sb + dstB + j * 128, srcB + kB * Bn + j * 32, 16);
        }
        cp_commit();

        uint32_t sb = sbase + (kc % STAGES) * STG_B;
#pragma unroll
        for (int ks = 0; ks < 4; ks++) {
            uint32_t ar[4][4], br[4][2];
#pragma unroll
            for (int mt = 0; mt < 4; mt++)
                ldsm4(ar[mt], sb + aRowOff + mt * 2304 + ks * 32);
            uint32_t ba = sb + bColOff + ks * (8 * 528);
#pragma unroll
            for (int nt = 0; nt < 4; nt++) {
                br[nt][0] = f2tf(ldsf(ba + nt * 32));
                br[nt][1] = f2tf(ldsf(ba + nt * 32 + 4 * 528));
            }
#pragma unroll
            for (int mt = 0; mt < 4; mt++)
#pragma unroll
                for (int nt = 0; nt < 4; nt++)
                    mma16n8k8(acc[mt][nt], ar[mt], br[nt]);
        }
    }

#pragma unroll
    for (int mt = 0; mt < 4; mt++) {
        int rl0 = mBase + warp_m * 64 + mt * 16 + g;
#pragma unroll
        for (int half = 0; half < 2; half++) {
            int rl = rl0 + half * 8;
            if (rl >= rows) continue;
            long cRow = row0 + rl;
            float* Crow = C + cRow * (long)ldc;
            const float* Rrow = resid ? (resid + cRow * (long)ldc) : (const float*)0;
#pragma unroll
            for (int nt = 0; nt < 4; nt++) {
                int c = nBase + warp_n * 32 + nt * 8 + 2 * t;
                float v0 = acc[mt][nt][half * 2 + 0];
                float v1 = acc[mt][nt][half * 2 + 1];
                if (bi)   { v0 += bi[c];   v1 += bi[c + 1]; }
                if (Rrow) { v0 += Rrow[c]; v1 += Rrow[c + 1]; }
                *(float2*)(Crow + c) = make_float2(v0, v1);
            }
        }
    }
}

__global__ void __launch_bounds__(256)
k_tgemm(const float* __restrict__ A, int lda,
        const float* __restrict__ Bmat, long bstride,
        const float* __restrict__ bias, long biasStride,
        const float* __restrict__ resid,
        float* __restrict__ C, int ldc,
        int M, int N, int K,
        const int* __restrict__ segoff,
        const int* __restrict__ rowmap) {
    int e = blockIdx.z;
    int row0 = 0, rows = M;
    if (segoff) { row0 = segoff[e]; rows = segoff[e + 1] - row0; }
    int mBase = blockIdx.y * 128;
    if (mBase >= rows) return;
    gemm_body(A, lda,
              Bmat + (long)e * bstride, N,
              bias ? (bias + (long)e * biasStride) : (const float*)0,
              resid, C, ldc,
              rows, row0, mBase, blockIdx.x * 128, K, rowmap);
}

/* fused Q/K/V projection: grid (12, 16); x<8 -> Q, 8..9 -> K, 10..11 -> V */
__global__ void __launch_bounds__(256)
k_qkv(const float* __restrict__ Wq, const float* __restrict__ Wk,
      const float* __restrict__ Wv) {
    int x = blockIdx.x;
    const float* B; float* C; int Bn, col0;
    if (x < 8)       { B = Wq; C = g_q; Bn = DM;      col0 = x * 128; }
    else if (x < 10) { B = Wk; C = g_k; Bn = NG * DK; col0 = (x - 8) * 128; }
    else             { B = Wv; C = g_v; Bn = NG * DK; col0 = (x - 10) * 128; }
    gemm_body(g_xr, DM, B, Bn, 0, 0, C, Bn,
              NTOK, 0, blockIdx.y * 128, col0, DM, 0);
}

/* ----------------- split-K flash attention (partials) ----------------------
   blockIdx.x enumerates (qt, kc) pairs: qt in 0..7, kc in 0..qt  (36 total).
   Each CTA: 128 query rows (qt*128..), 128 keys (kc*128..), partial m/l/o.
   Partials: o -> g_h1  [(kc*64+d)*NROWS + r], (m,l) -> g_h2 as float2[r*8+kc]
   (g_h1/g_h2 are free until the MoE phase).                                 */
__global__ void __launch_bounds__(128)
k_attn_split() {
    int fx = blockIdx.x;
    int qt = 0;
#pragma unroll
    for (int q = 1; q < 8; q++) if (fx >= (q * (q + 1)) / 2) qt = q;
    int kc = fx - (qt * (qt + 1)) / 2;
    int h  = blockIdx.y;
    int b  = blockIdx.z;
    int g  = h / HPG;
    int tid = threadIdx.x;
    int i  = qt * 128 + tid;
    bool diag = (kc == qt);

    __shared__ float Ks[64][DK];
    __shared__ float Vs[64][DK];

    float q[DK];
    const float* qp = g_q + ((size_t)(b * SEQ + i)) * DM + h * DK;
#pragma unroll
    for (int d = 0; d < DK; d++) q[d] = qp[d] * 0.125f;

    float o[DK];
#pragma unroll
    for (int d = 0; d < DK; d++) o[d] = 0.f;
    float m = -1e30f, l = 0.f;

    for (int kt = 0; kt < 2; kt++) {
        int j0 = kc * 128 + kt * 64;
        __syncthreads();
        for (int tt = tid; tt < 64 * DK; tt += 128) {
            int jj = tt / DK, d = tt % DK;
            size_t src = ((size_t)(b * SEQ + j0 + jj)) * (NG * DK) + g * DK + d;
            Ks[jj][d] = g_k[src];
            Vs[jj][d] = g_v[src];
        }
        __syncthreads();

        for (int c0 = 0; c0 < 64; c0 += 32) {
            float s[32];
            for (int jj = 0; jj < 32; jj++) {
                float acc = 0.f;
#pragma unroll
                for (int d = 0; d < DK; d++) acc += q[d] * Ks[c0 + jj][d];
                bool ok = !diag || (j0 + c0 + jj <= i);
                s[jj] = ok ? acc : -1e30f;
            }
            float mn = m;
            for (int jj = 0; jj < 32; jj++) mn = fmaxf(mn, s[jj]);
            float scale = __expf(m - mn);
            m = mn;
            l *= scale;
#pragma unroll
            for (int d = 0; d < DK; d++) o[d] *= scale;
            for (int jj = 0; jj < 32; jj++) {
                bool ok = !diag || (j0 + c0 + jj <= i);
                float p = ok ? __expf(s[jj] - mn) : 0.f;
                l += p;
#pragma unroll
                for (int d = 0; d < DK; d++) o[d] += p * Vs[c0 + jj][d];
            }
        }
    }

    int r = ((b * NH + h) << 10) + i;     /* SEQ = 1024 */
    float* po = g_h1;
#pragma unroll
    for (int d = 0; d < DK; d++)
        po[((size_t)(kc * DK + d)) * NROWS + r] = o[d];
    ((float2*)g_h2)[r * 8 + kc] = make_float2(m, l);
}

/* combine partials -> g_attn (tf32-rounded). One thread per row. */
__global__ void __launch_bounds__(256)
k_attn_combine() {
    int r = blockIdx.x * 256 + threadIdx.x;   /* 0..NROWS-1 */
    int s  = r & (SEQ - 1);
    int hb = r >> 10;
    int h  = hb & (NH - 1);
    int b  = hb >> 4;
    int nch = (s >> 7) + 1;

    const float*  po = g_h1;
    const float2* ml = (const float2*)g_h2;

    float2 mlc[8];
    float M = -1e30f;
    for (int c = 0; c < nch; c++) {
        mlc[c] = ml[r * 8 + c];
        M = fmaxf(M, mlc[c].x);
    }
    float w[8];
    float l = 0.f;
    for (int c = 0; c < nch; c++) {
        w[c] = __expf(mlc[c].x - M);
        l += w[c] * mlc[c].y;
    }
    float invl = 1.f / l;

    float* op = g_attn + ((size_t)(b * SEQ + s)) * DM + h * DK;
#pragma unroll
    for (int d = 0; d < DK; d++) {
        float acc = 0.f;
        for (int c = 0; c < nch; c++)
            acc += w[c] * po[((size_t)(c * DK + d)) * NROWS + r];
        op[d] = f2tff(acc * invl);
    }
}

/* ------------------------------- MoE routing ------------------------------ */

__global__ void k_router(const float* __restrict__ rw,
                         const float* __restrict__ rb) {
    int t    = blockIdx.x * 8 + (threadIdx.x >> 5);
    int lane = threadIdx.x & 31;
    float part[NE];
#pragma unroll
    for (int e = 0; e < NE; e++) part[e] = 0.f;
    const float* hp = g_hn + (size_t)t * DM;
    for (int d = lane; d < DM; d += 32) {
        float hv = hp[d];
        const float* rp = rw + (size_t)d * NE;
#pragma unroll
        for (int e = 0; e < NE; e++) part[e] += hv * rp[e];
    }
#pragma unroll
    for (int e = 0; e < NE; e++)
        for (int off = 16; off > 0; off >>= 1)
            part[e] += __shfl_xor_sync(0xffffffffu, part[e], off);
    if (lane == 0) {
        float lg[NE];
#pragma unroll
        for (int e = 0; e < NE; e++) lg[e] = part[e] + rb[e];
        int i0 = 0;
        for (int e = 1; e < NE; e++) if (lg[e] > lg[i0]) i0 = e;
        int i1 = (i0 == 0) ? 1 : 0;
        for (int e = 0; e < NE; e++)
            if (e != i0 && lg[e] > lg[i1]) i1 = e;
        float e1 = __expf(lg[i1] - lg[i0]);
        float inv = 1.f / (1.f + e1);
        g_tidx[t * 2 + 0] = i0; g_tidx[t * 2 + 1] = i1;
        g_twgt[t * 2 + 0] = inv; g_twgt[t * 2 + 1] = e1 * inv;
        atomicAdd(&g_cnt[i0], 1);
        atomicAdd(&g_cnt[i1], 1);
    }
}

__global__ void k_scan() {
    if (threadIdx.x == 0) {
        int acc = 0;
        for (int e = 0; e < NE; e++) {
            g_off[e] = acc; acc += g_cnt[e]; g_cur[e] = 0;
        }
        g_off[NE] = acc;
    }
}

__global__ void k_scatter() {
    int t = blockIdx.x * 256 + threadIdx.x;
    if (t >= NTOK) return;
#pragma unroll
    for (int k = 0; k < 2; k++) {
        int e = g_tidx[t * 2 + k];
        int p = atomicAdd(&g_cur[e], 1);
        int row = g_off[e] + p;
        g_tok[row] = t;
        g_trow[t * 2 + k] = row;
    }
}

__global__ void k_silu() {
    size_t i = ((size_t)blockIdx.x * 256 + threadIdx.x) * 4;
    float4 a = *(float4*)&g_h1[i];
    float4 b = *(float4*)&g_h2[i];
    a.x = f2tff(b.x * a.x / (1.f + __expf(-a.x)));
    a.y = f2tff(b.y * a.y / (1.f + __expf(-a.y)));
    a.z = f2tff(b.z * a.z / (1.f + __expf(-a.z)));
    a.w = f2tff(b.w * a.w / (1.f + __expf(-a.w)));
    *(float4*)&g_h1[i] = a;
}

__global__ void k_combine(float* __restrict__ out) {
    int t = blockIdx.x;
    int   r0 = g_trow[t * 2],     r1 = g_trow[t * 2 + 1];
    float w0 = g_twgt[t * 2],     w1 = g_twgt[t * 2 + 1];
    const float* e0 = g_eo + (size_t)r0 * DM;
    const float* e1 = g_eo + (size_t)r1 * DM;
    float* op = out + (size_t)t * DM;
    for (int d = threadIdx.x; d < DM; d += 256)
        op[d] += w0 * e0[d] + w1 * e1[d];
}

/* --------------------------------- driver --------------------------------- */

extern "C" void kernel_launch(void* const* d_in, const int* in_sizes, int n_in,
                              void* d_out, int out_size) {
    const float* x   = (const float*)d_in[0];
    const float* n1w = (const float*)d_in[1];
    const float* Wq  = (const float*)d_in[2];
    const float* Wk  = (const float*)d_in[3];
    const float* Wv  = (const float*)d_in[4];
    const float* Wo  = (const float*)d_in[5];
    const float* n2w = (const float*)d_in[6];
    const float* rw  = (const float*)d_in[7];
    const float* rb  = (const float*)d_in[8];
    const float* W1  = (const float*)d_in[9];
    const float* b1  = (const float*)d_in[10];
    const float* W2  = (const float*)d_in[11];
    const float* b2  = (const float*)d_in[12];
    const float* W3  = (const float*)d_in[13];
    const float* b3  = (const float*)d_in[14];
    float* out = (float*)d_out;

    cudaFuncSetAttribute(k_tgemm, cudaFuncAttributeMaxDynamicSharedMemorySize,
                         TG_SMEM);
    cudaFuncSetAttribute(k_qkv, cudaFuncAttributeMaxDynamicSharedMemorySize,
                         TG_SMEM);

    void *p_attn, *p_hnr, *p_h1, *p_h2, *p_eo, *p_off, *p_tok;
    cudaGetSymbolAddress(&p_attn, g_attn);
    cudaGetSymbolAddress(&p_hnr,  g_hnr);
    cudaGetSymbolAddress(&p_h1,   g_h1);
    cudaGetSymbolAddress(&p_h2,   g_h2);
    cudaGetSymbolAddress(&p_eo,   g_eo);
    cudaGetSymbolAddress(&p_off,  g_off);
    cudaGetSymbolAddress(&p_tok,  g_tok);
    float* attn = (float*)p_attn;
    float* hnr  = (float*)p_hnr;
    float* h1b  = (float*)p_h1;
    float* h2b  = (float*)p_h2;
    float* eob  = (float*)p_eo;
    int*   offp = (int*)p_off;
    int*   tokp = (int*)p_tok;

    k_zero<<<1, 32>>>();
    k_norm_rope<<<NTOK, 256>>>(x, n1w);

    /* fused Q/K/V projections */
    k_qkv<<<dim3(12, NTOK/128, 1), 256, TG_SMEM>>>(Wq, Wk, Wv);

    /* split-K flash attention: partials, then combine */
    k_attn_split<<<dim3(36, NH, BATCH), 128>>>();
    k_attn_combine<<<NROWS/256, 256>>>();

    /* out = x + attn @ Wo */
    k_tgemm<<<dim3(DM/128, NTOK/128, 1), 256, TG_SMEM>>>(
        attn, DM, Wo, 0, 0, 0, x, out, DM, NTOK, DM, DM, 0, 0);

    k_rmsnorm<<<NTOK, 256>>>(out, n2w);

    k_router<<<NTOK/8, 256>>>(rw, rb);
    k_scan<<<1, 32>>>();
    k_scatter<<<NTOK/256, 256>>>();

    /* expert FFN */
    k_tgemm<<<dim3(DFF/128, NTOK/128, NE), 256, TG_SMEM>>>(
        hnr, DM, W1, (long)DM*DFF, b1, DFF, 0,
        h1b, DFF, 0, DFF, DM, offp, tokp);
    k_tgemm<<<dim3(DFF/128, NTOK/128, NE), 256, TG_SMEM>>>(
        hnr, DM, W2, (long)DM*DFF, b2, DFF, 0,
        h2b, DFF, 0, DFF, DM, offp, tokp);
    k_silu<<<(NASSIGN*(DFF/4))/256, 256>>>();
    k_tgemm<<<dim3(DM/128, NTOK/128, NE), 256, TG_SMEM>>>(
        h1b, DFF, W3, (long)DFF*DM, b3, DM, 0,
        eob, DM, 0, DM, DFF, offp, 0);

    k_combine<<<NTOK, 256>>>(out);
}